// round 5
// baseline (speedup 1.0000x reference)
#include <cuda_runtime.h>
#include <cuda_bf16.h>
#include <cstdint>

// Problem constants
#define BB      32
#define CC      256
#define HW      1024           // 32*32
#define NTOT    32768          // BB*HW
#define KK      1024
#define NQ      8388608        // BB*CC*HW

#define TN      32             // n per block
#define TKC     32             // codes per tile
#define NKT     (KK / TKC)     // 32 code tiles
#define WST     34             // ws row stride (d-major, k contiguous), even for LDS.64 align
#define THREADS 128

typedef unsigned long long u64;

// Scratch
__device__ double g_loss;
__device__ int    g_idx[NTOT];
__device__ float  g_wnorm[KK];
__device__ float  g_zn2[NTOT];

#define FFMA2(acc, a, b) \
    asm("fma.rn.f32x2 %0, %1, %2, %0;" : "+l"(acc) : "l"(a), "l"(b))
#define PACK2(out, lo, hi) \
    asm("mov.b64 %0, {%1, %2};" : "=l"(out) : "f"(lo), "f"(hi))
#define UNPACK2(lo, hi, in) \
    asm("mov.b64 {%0, %1}, %2;" : "=f"(lo), "=f"(hi) : "l"(in))

// ---------------------------------------------------------------------------
// Kernel 1: ||w_k||^2 in double (order-insensitive vs 3e-5 plateau) + loss init
// ---------------------------------------------------------------------------
__global__ void wnorm_kernel(const float* __restrict__ w) {
    int k = blockIdx.x * 256 + threadIdx.x;
    if (k == 0) g_loss = 0.0;
    const float* row = w + (size_t)k * CC;
    double s = 0.0;
    #pragma unroll 8
    for (int i = 0; i < CC; i++) { double v = (double)row[i]; s += v * v; }
    g_wnorm[k] = (float)s;
}

// ---------------------------------------------------------------------------
// Kernel 2: zn2[n] — exact XLA row-reduce emulation (vec=2, 4 warp trees,
// (W0+W2)+(W1+W3)). DO NOT CHANGE: bitwise-matched to reference (rel_err 0.0).
// ---------------------------------------------------------------------------
__global__ void zn2_kernel(const float* __restrict__ z) {
    const int n  = blockIdx.x * 256 + threadIdx.x;
    const int b  = n >> 10;
    const int hw = n & (HW - 1);
    const float* row = z + (size_t)b * (CC * HW) + hw;

    float W[4];
    #pragma unroll
    for (int w4 = 0; w4 < 4; w4++) {
        float p[32];
        #pragma unroll
        for (int l = 0; l < 32; l++) {
            float a = row[(size_t)(64 * w4 + 2 * l) * HW];
            float c = row[(size_t)(64 * w4 + 2 * l + 1) * HW];
            p[l] = __fadd_rn(__fmul_rn(a, a), __fmul_rn(c, c));
        }
        #pragma unroll
        for (int off = 16; off >= 1; off >>= 1)
            #pragma unroll
            for (int l = 0; l < 16; l++)
                if (l < off) p[l] = __fadd_rn(p[l], p[l + off]);
        W[w4] = p[0];
    }
    g_zn2[n] = __fadd_rn(__fadd_rn(W[0], W[2]), __fadd_rn(W[1], W[3]));
}

// ---------------------------------------------------------------------------
// Kernel 3: argmin. Block = 32 n, 128 threads, 3 CTAs/SM.
// Per-thread tile 4n x 2k. FFMA2 with swap-trick: accd = {n0k0,n1k1},
// accx = {n0k1,n1k0}. dot = ascending-d fp32 chain per (n,k) (exactness).
// Shared (floats): zs[256*32]=8192 | ws[256*34]=8704  (67.6 KB total)
// ---------------------------------------------------------------------------
__global__ __launch_bounds__(THREADS, 3)
void argmin_kernel(const float* __restrict__ z, const float* __restrict__ w) {
    extern __shared__ float sm[];
    float* zs = sm;            // 8192 floats, row stride 32 (d-major)
    float* ws = sm + 8192;     // 8704 floats, row stride 34 (d-major, k contig)

    const int t     = threadIdx.x;
    const int ntile = blockIdx.x;            // 0..1023
    const int b     = ntile >> 5;            // 32 tiles per image
    const int hw0   = (ntile & 31) * TN;
    const float* zb = z + (size_t)b * (CC * HW) + hw0;

    // Load z tile: zs[d][n], coalesced float4
    #pragma unroll
    for (int j = 0; j < 16; j++) {
        int chunk = j * THREADS + t;
        int d  = chunk >> 3;
        int n4 = chunk & 7;
        *(float4*)&zs[d * TN + n4 * 4] = *(const float4*)&zb[(size_t)d * HW + n4 * 4];
    }

    const int ng = (t & 7) * 4;              // this thread's 4 n's
    const int kg = (t >> 3) * 2;             // this thread's 2 local k's
    float znv[4];
    #pragma unroll
    for (int j = 0; j < 4; j++) znv[j] = g_zn2[ntile * TN + ng + j];

    const int kk   = t & 31;                 // w row to load
    const int part = t >> 5;                 // 64-d quarter
    const float* zp = zs + ng;
    const float* wp = ws + kg;

    float minv[4] = {1e30f, 1e30f, 1e30f, 1e30f};
    int   mini[4] = {0, 0, 0, 0};

    for (int kt = 0; kt < NKT; kt++) {
        __syncthreads();   // previous ws fully consumed (and zs stores done, kt=0)
        // Load w tile rows [kt*32 .. kt*32+32), transpose into ws[d][k]
        {
            const float* src = w + (size_t)(kt * TKC + kk) * CC + part * 64;
            #pragma unroll
            for (int j = 0; j < 16; j++) {
                float4 v = *(const float4*)(src + j * 4);
                int d0 = part * 64 + j * 4;
                ws[(d0 + 0) * WST + kk] = v.x;
                ws[(d0 + 1) * WST + kk] = v.y;
                ws[(d0 + 2) * WST + kk] = v.z;
                ws[(d0 + 3) * WST + kk] = v.w;
            }
        }
        const int k0  = kt * TKC + kg;
        float wn0 = __ldg(&g_wnorm[k0]);
        float wn1 = __ldg(&g_wnorm[k0 + 1]);
        __syncthreads();   // ws ready

        u64 accd0 = 0, accx0 = 0, accd1 = 0, accx1 = 0;
        #pragma unroll 8
        for (int d = 0; d < CC; d++) {
            ulonglong2 av = *(const ulonglong2*)(zp + d * TN);   // {n0,n1},{n2,n3}
            float2 bv = *(const float2*)(wp + d * WST);          // {k0, k1}
            u64 bp, bs;
            PACK2(bp, bv.x, bv.y);
            PACK2(bs, bv.y, bv.x);
            FFMA2(accd0, av.x, bp);   // {n0*k0, n1*k1}
            FFMA2(accx0, av.x, bs);   // {n0*k1, n1*k0}
            FFMA2(accd1, av.y, bp);   // {n2*k0, n3*k1}
            FFMA2(accx1, av.y, bs);   // {n2*k1, n3*k0}
        }

        float dd0l, dd0h, dx0l, dx0h, dd1l, dd1h, dx1l, dx1h;
        UNPACK2(dd0l, dd0h, accd0);
        UNPACK2(dx0l, dx0h, accx0);
        UNPACK2(dd1l, dd1h, accd1);
        UNPACK2(dx1l, dx1h, accx1);
        float dot0[4] = {dd0l, dx0h, dd1l, dx1h};   // k = k0
        float dot1[4] = {dx0l, dd0h, dx1l, dd1h};   // k = k0+1

        // dist exactly as reference: fl(fl(zn2 - 2*dot) + wn); ascending k,
        // strict < keeps the lowest index on quantized ties.
        #pragma unroll
        for (int j = 0; j < 4; j++) {
            float t1 = __fmaf_rn(-2.0f, dot0[j], znv[j]);
            float d2 = __fadd_rn(t1, wn0);
            if (d2 < minv[j]) { minv[j] = d2; mini[j] = k0; }
        }
        #pragma unroll
        for (int j = 0; j < 4; j++) {
            float t1 = __fmaf_rn(-2.0f, dot1[j], znv[j]);
            float d2 = __fadd_rn(t1, wn1);
            if (d2 < minv[j]) { minv[j] = d2; mini[j] = k0 + 1; }
        }
    }

    // Cross-thread reduction over 16 k-rows per n (reuse zs)
    __syncthreads();
    float* rv = zs;                  // [16][32]
    int*   ri = (int*)(zs + 512);    // [16][32]
    const int r = t >> 3;
    #pragma unroll
    for (int j = 0; j < 4; j++) {
        rv[r * TN + ng + j] = minv[j];
        ri[r * TN + ng + j] = mini[j];
    }
    __syncthreads();
    if (t < TN) {
        float bv = rv[t];
        int   bi = ri[t];
        #pragma unroll
        for (int r2 = 1; r2 < 16; r2++) {
            float v  = rv[r2 * TN + t];
            int   i2 = ri[r2 * TN + t];
            if (v < bv || (v == bv && i2 < bi)) { bv = v; bi = i2; }
        }
        g_idx[ntile * TN + t] = bi;
    }
}

// ---------------------------------------------------------------------------
// Kernel 4: gather z_q (float4) + fused MSE; ONE atomic per block
// ---------------------------------------------------------------------------
#define GBLOCKS 2048
__global__ void gather_kernel(const float* __restrict__ z,
                              const float* __restrict__ w,
                              float* __restrict__ out) {
    const int tid = blockIdx.x * 256 + threadIdx.x;   // 524288 threads
    double s = 0.0;
    #pragma unroll
    for (int rep = 0; rep < 4; rep++) {
        const int e4 = tid + rep * (GBLOCKS * 256);
        const int g  = e4 * 4;
        const int hw = g & (HW - 1);
        const int c  = (g >> 10) & (CC - 1);
        const int b  = g >> 18;
        int4  iv = *(const int4*)(g_idx + (b << 10) + hw);
        float4 zv = *(const float4*)(z + g);
        float4 ov;
        ov.x = __ldg(&w[(size_t)iv.x * CC + c]);
        ov.y = __ldg(&w[(size_t)iv.y * CC + c]);
        ov.z = __ldg(&w[(size_t)iv.z * CC + c]);
        ov.w = __ldg(&w[(size_t)iv.w * CC + c]);
        *(float4*)(out + g) = ov;
        float dx = zv.x - ov.x, dy = zv.y - ov.y, dz = zv.z - ov.z, dw = zv.w - ov.w;
        s += (double)dx * dx + (double)dy * dy + (double)dz * dz + (double)dw * dw;
    }
    #pragma unroll
    for (int o = 16; o; o >>= 1) s += __shfl_xor_sync(0xffffffffu, s, o);
    __shared__ double bs[8];
    const int lane = threadIdx.x & 31, wid = threadIdx.x >> 5;
    if (lane == 0) bs[wid] = s;
    __syncthreads();
    if (threadIdx.x == 0) {
        double tot = 0.0;
        #pragma unroll
        for (int i = 0; i < 8; i++) tot += bs[i];
        atomicAdd(&g_loss, tot);
    }
}

__global__ void finalize_kernel(float* __restrict__ out, int out_size) {
    float loss = (float)(g_loss * (1.0 / (double)NQ));
    if (out_size >= NQ + 1) out[NQ] = loss;
    if (out_size >= NQ + 2) out[NQ + 1] = loss;
}

// ---------------------------------------------------------------------------
extern "C" void kernel_launch(void* const* d_in, const int* in_sizes, int n_in,
                              void* d_out, int out_size) {
    const float* z = (const float*)d_in[0];
    const float* w = (const float*)d_in[1];
    float* out = (float*)d_out;

    const int smem = (8192 + CC * WST) * (int)sizeof(float);   // 67584 B
    cudaFuncSetAttribute(argmin_kernel, cudaFuncAttributeMaxDynamicSharedMemorySize, smem);

    wnorm_kernel<<<KK / 256, 256>>>(w);
    zn2_kernel<<<NTOT / 256, 256>>>(z);
    argmin_kernel<<<NTOT / TN, THREADS, smem>>>(z, w);
    gather_kernel<<<GBLOCKS, 256>>>(z, w, out);
    finalize_kernel<<<1, 1>>>(out, out_size);
}

// round 11
// speedup vs baseline: 1.4431x; 1.4431x over previous
#include <cuda_runtime.h>
#include <cuda_bf16.h>
#include <cstdint>

// Problem constants
#define BB      32
#define CC      256
#define HW      1024
#define NTOT    32768          // BB*HW
#define KK      1024
#define NQ      8388608        // BB*CC*HW
#define MARGIN  4e-4f

typedef unsigned long long u64;

// Scratch (static device globals only — no runtime alloc)
__device__ double   g_loss;
__device__ int      g_idx[NTOT];
__device__ float    g_wnorm[KK];
__device__ float    g_zn2[NTOT];
__device__ uint32_t g_wpack[131072];     // 1024x256 bf16, fragment-ordered (512KB)
__device__ int      g_cand[NTOT * 8];    // candidate ks for status-1 tokens
__device__ int      g_stat[NTOT];        // 0=done, 1=rescore cands, 2=full scan

// ---------------------------------------------------------------------------
// Kernel 1: ||w_k||^2 in double (order-insensitive vs 3e-5 plateau) + loss init
// ---------------------------------------------------------------------------
__global__ void wnorm_kernel(const float* __restrict__ w) {
    int k = blockIdx.x * 256 + threadIdx.x;
    if (k == 0) g_loss = 0.0;
    const float* row = w + (size_t)k * CC;
    double s = 0.0;
    #pragma unroll 8
    for (int i = 0; i < CC; i++) { double v = (double)row[i]; s += v * v; }
    g_wnorm[k] = (float)s;
}

// ---------------------------------------------------------------------------
// Kernel 2: zn2 — exact XLA row-reduce emulation. DO NOT CHANGE (rel_err 0.0).
// ---------------------------------------------------------------------------
__global__ void zn2_kernel(const float* __restrict__ z) {
    const int n  = blockIdx.x * 256 + threadIdx.x;
    const int b  = n >> 10;
    const int hw = n & (HW - 1);
    const float* row = z + (size_t)b * (CC * HW) + hw;
    float W[4];
    #pragma unroll
    for (int w4 = 0; w4 < 4; w4++) {
        float p[32];
        #pragma unroll
        for (int l = 0; l < 32; l++) {
            float a = row[(size_t)(64 * w4 + 2 * l) * HW];
            float c = row[(size_t)(64 * w4 + 2 * l + 1) * HW];
            p[l] = __fadd_rn(__fmul_rn(a, a), __fmul_rn(c, c));
        }
        #pragma unroll
        for (int off = 16; off >= 1; off >>= 1)
            #pragma unroll
            for (int l = 0; l < 16; l++)
                if (l < off) p[l] = __fadd_rn(p[l], p[l + off]);
        W[w4] = p[0];
    }
    g_zn2[n] = __fadd_rn(__fadd_rn(W[0], W[2]), __fadd_rn(W[1], W[3]));
}

// ---------------------------------------------------------------------------
// Kernel 3: pack w into mma B-fragment order (bf16).
// Slot idx = (nb*16 + ks)*32 + t; code = nb*8 + t/4; c = t%4; d0 = ks*16+2c.
// reg0 = {w[code][d0], w[code][d0+1]}, reg1 = {w[code][d0+8], w[code][d0+9]}.
// ---------------------------------------------------------------------------
__global__ void wpack_kernel(const float* __restrict__ w) {
    int idx = blockIdx.x * 256 + threadIdx.x;        // 65536 slots
    int t = idx & 31, ks = (idx >> 5) & 15, nb = idx >> 9;
    int code = nb * 8 + (t >> 2);
    int c = t & 3;
    int d0 = ks * 16 + 2 * c;
    const float* wr = w + (size_t)code * CC;
    __nv_bfloat162 r0 = __floats2bfloat162_rn(wr[d0],     wr[d0 + 1]);
    __nv_bfloat162 r1 = __floats2bfloat162_rn(wr[d0 + 8], wr[d0 + 9]);
    g_wpack[idx * 2]     = *(uint32_t*)&r0;
    g_wpack[idx * 2 + 1] = *(uint32_t*)&r1;
}

// ---------------------------------------------------------------------------
// Kernel 4: bf16 mma.sync argmin. CTA = 128 tokens, 128 threads (4 warps).
// Warp owns 32 tokens (two m16 groups); sweeps 1024 codes in 16 n64-tiles.
// Smem: apack[16384 u32] (A fragments bf16) | stage[4096 f] | wns[1024 f]
// Per token-row: track (min1,k1),(min2,k2),min3; certify unique-in-margin,
// else hand off to cleanup (cands or full-scan).
// ---------------------------------------------------------------------------
#define UPD(mg, h, s, k) do { \
    if ((s) < v1[mg][h]) { v3[mg][h] = v2[mg][h]; v2[mg][h] = v1[mg][h]; \
        k2[mg][h] = k1[mg][h]; v1[mg][h] = (s); k1[mg][h] = (k); } \
    else if ((s) < v2[mg][h]) { v3[mg][h] = v2[mg][h]; v2[mg][h] = (s); k2[mg][h] = (k); } \
    else if ((s) < v3[mg][h]) { v3[mg][h] = (s); } \
} while (0)

#define MMA_BF16(C, A, b0, b1) \
    asm volatile("mma.sync.aligned.m16n8k16.row.col.f32.bf16.bf16.f32 " \
        "{%0,%1,%2,%3}, {%4,%5,%6,%7}, {%8,%9}, {%0,%1,%2,%3};" \
        : "+f"((C)[0]), "+f"((C)[1]), "+f"((C)[2]), "+f"((C)[3]) \
        : "r"((A).x), "r"((A).y), "r"((A).z), "r"((A).w), "r"(b0), "r"(b1))

__global__ __launch_bounds__(128, 2)
void mma_argmin_kernel(const float* __restrict__ z, const float* __restrict__ w) {
    extern __shared__ uint32_t smu[];
    uint32_t* apack = smu;                        // 16384 u32 (64KB)
    float*    stage = (float*)(smu + 16384);      // 4096 f (16KB)
    float*    wns   = (float*)(smu + 20480);      // 1024 f (4KB)

    const int t = threadIdx.x, wp = t >> 5, lane = t & 31;
    const int c4 = lane & 3;
    const int n0  = blockIdx.x * 128;
    const int b   = blockIdx.x >> 3;
    const int hw0 = (blockIdx.x & 7) * 128;
    const float* zb = z + (size_t)b * (CC * HW) + hw0;

    #pragma unroll
    for (int j = 0; j < 8; j++) wns[j * 128 + t] = g_wnorm[j * 128 + t];

    // ---- pack A (z rows) into fragment-ordered bf16 smem, 32-d chunks ----
    for (int cd = 0; cd < 8; cd++) {
        __syncthreads();
        #pragma unroll
        for (int j = 0; j < 8; j++) {
            int fi = j * 128 + t;
            int dl = fi >> 5, h4 = fi & 31;
            *(float4*)&stage[dl * 128 + h4 * 4] =
                *(const float4*)&zb[(size_t)(cd * 32 + dl) * HW + h4 * 4];
        }
        __syncthreads();
        #pragma unroll
        for (int i = 0; i < 16; i++) {
            int slot = i * 128 + t;
            int ai = slot & 3, tid2 = (slot >> 2) & 31;
            int rp = (slot >> 7) & 1, wp2 = (slot >> 8) & 3, ksl = (slot >> 10) & 1;
            int tok  = wp2 * 32 + rp * 16 + (ai & 1) * 8 + (tid2 >> 2);
            int dloc = ksl * 16 + ((ai >> 1) & 1) * 8 + 2 * (tid2 & 3);
            __nv_bfloat162 v = __floats2bfloat162_rn(stage[dloc * 128 + tok],
                                                     stage[(dloc + 1) * 128 + tok]);
            int ks = cd * 2 + ksl;
            apack[(ks * 8 + wp2 * 2 + rp) * 128 + tid2 * 4 + ai] = *(uint32_t*)&v;
        }
    }
    __syncthreads();

    const uint4* ap4 = (const uint4*)apack;
    const uint2* wpg = (const uint2*)g_wpack;

    float v1[2][2], v2[2][2], v3[2][2];
    int   k1[2][2], k2[2][2];
    #pragma unroll
    for (int a = 0; a < 2; a++)
        #pragma unroll
        for (int h = 0; h < 2; h++) {
            v1[a][h] = v2[a][h] = v3[a][h] = 1e30f;
            k1[a][h] = k2[a][h] = 0x7fffffff;
        }

    for (int nt = 0; nt < 16; nt++) {
        float acc[2][8][4];
        #pragma unroll
        for (int a = 0; a < 2; a++)
            #pragma unroll
            for (int nb = 0; nb < 8; nb++)
                #pragma unroll
                for (int r = 0; r < 4; r++) acc[a][nb][r] = 0.f;

        #pragma unroll
        for (int ks = 0; ks < 16; ks++) {
            uint4 A0 = ap4[(ks * 8 + wp * 2 + 0) * 32 + lane];
            uint4 A1 = ap4[(ks * 8 + wp * 2 + 1) * 32 + lane];
            #pragma unroll
            for (int nb = 0; nb < 8; nb++) {
                uint2 Bv = wpg[((nt * 8 + nb) * 16 + ks) * 32 + lane];
                MMA_BF16(acc[0][nb], A0, Bv.x, Bv.y);
                MMA_BF16(acc[1][nb], A1, Bv.x, Bv.y);
            }
        }
        // epilogue: s = wn - 2*dot; track top candidates per token-row
        #pragma unroll
        for (int nb = 0; nb < 8; nb++) {
            int kb = nt * 64 + nb * 8 + 2 * c4;
            float2 wnp = *(const float2*)&wns[kb];
            #pragma unroll
            for (int mg = 0; mg < 2; mg++) {
                float s0 = __fmaf_rn(-2.f, acc[mg][nb][0], wnp.x);
                float s1 = __fmaf_rn(-2.f, acc[mg][nb][1], wnp.y);
                float s2 = __fmaf_rn(-2.f, acc[mg][nb][2], wnp.x);
                float s3 = __fmaf_rn(-2.f, acc[mg][nb][3], wnp.y);
                UPD(mg, 0, s0, kb); UPD(mg, 0, s1, kb + 1);
                UPD(mg, 1, s2, kb); UPD(mg, 1, s3, kb + 1);
            }
        }
    }

    // ---- per token-row: quad-combine, certify or hand off ----
    #pragma unroll
    for (int mg = 0; mg < 2; mg++)
        #pragma unroll
        for (int h = 0; h < 2; h++) {
            float gm = v1[mg][h];
            gm = fminf(gm, __shfl_xor_sync(0xffffffffu, gm, 1));
            gm = fminf(gm, __shfl_xor_sync(0xffffffffu, gm, 2));
            float thr = gm + MARGIN;
            int c1 = v1[mg][h] <= thr;
            int c2 = v2[mg][h] <= thr;
            int ov = v3[mg][h] <= thr;
            int tot = c1 + c2;
            tot += __shfl_xor_sync(0xffffffffu, tot, 1);
            tot += __shfl_xor_sync(0xffffffffu, tot, 2);
            ov |= __shfl_xor_sync(0xffffffffu, ov, 1);
            ov |= __shfl_xor_sync(0xffffffffu, ov, 2);
            int kw = c1 ? k1[mg][h] : 0x7fffffff;
            kw = min(kw, __shfl_xor_sync(0xffffffffu, kw, 1));
            kw = min(kw, __shfl_xor_sync(0xffffffffu, kw, 2));
            int n  = n0 + wp * 32 + mg * 16 + h * 8 + (lane >> 2);
            int st = ov ? 2 : (tot == 1 ? 0 : 1);
            if (st == 1) {
                g_cand[n * 8 + c4 * 2]     = c1 ? k1[mg][h] : -1;
                g_cand[n * 8 + c4 * 2 + 1] = c2 ? k2[mg][h] : -1;
            }
            if (c4 == 0) {
                if (st == 0) g_idx[n] = kw;
                g_stat[n] = st;
            }
        }
}

// ---------------------------------------------------------------------------
// Kernel 5: cleanup — exact rescore (bit-exact ascending-d fp32 chain +
// quantized dist + lowest-k tie) for uncertified tokens. Warp per token.
// ---------------------------------------------------------------------------
__global__ void cleanup_kernel(const float* __restrict__ z, const float* __restrict__ w) {
    __shared__ float zbuf[8][256];
    const int wid = threadIdx.x >> 5, lane = threadIdx.x & 31;
    const int gw = blockIdx.x * 8 + wid;          // 2048 warps
    for (int n = gw; n < NTOT; n += 2048) {
        int st = g_stat[n];
        if (st == 0) continue;
        int b = n >> 10, hw = n & (HW - 1);
        const float* zr = z + (size_t)b * (CC * HW) + hw;
        #pragma unroll
        for (int j = 0; j < 8; j++)
            zbuf[wid][lane + j * 32] = zr[(size_t)(lane + j * 32) * HW];
        __syncwarp();
        float zn2v = g_zn2[n];
        float bv = 1e30f; int bk = 0x7fffffff;
        if (st == 1) {
            if (lane < 8) {
                int k = g_cand[n * 8 + lane];
                if (k >= 0) {
                    const float* wr = w + (size_t)k * CC;
                    float acc = 0.f;
                    #pragma unroll 8
                    for (int d = 0; d < CC; d++)
                        acc = __fmaf_rn(zbuf[wid][d], wr[d], acc);
                    bv = __fadd_rn(__fmaf_rn(-2.f, acc, zn2v), g_wnorm[k]);
                    bk = k;
                }
            }
        } else {
            for (int k = lane; k < KK; k += 32) {
                const float* wr = w + (size_t)k * CC;
                float acc = 0.f;
                #pragma unroll 8
                for (int d = 0; d < CC; d++)
                    acc = __fmaf_rn(zbuf[wid][d], wr[d], acc);
                float d2 = __fadd_rn(__fmaf_rn(-2.f, acc, zn2v), g_wnorm[k]);
                if (d2 < bv) { bv = d2; bk = k; }
            }
        }
        #pragma unroll
        for (int o = 16; o; o >>= 1) {
            float ov2 = __shfl_xor_sync(0xffffffffu, bv, o);
            int   ok2 = __shfl_xor_sync(0xffffffffu, bk, o);
            if (ov2 < bv || (ov2 == bv && ok2 < bk)) { bv = ov2; bk = ok2; }
        }
        if (lane == 0) g_idx[n] = bk;
        __syncwarp();
    }
}

// ---------------------------------------------------------------------------
// Kernel 6: gather z_q (float4) + fused MSE; one atomic per block
// ---------------------------------------------------------------------------
#define GBLOCKS 2048
__global__ void gather_kernel(const float* __restrict__ z,
                              const float* __restrict__ w,
                              float* __restrict__ out) {
    const int tid = blockIdx.x * 256 + threadIdx.x;
    double s = 0.0;
    #pragma unroll
    for (int rep = 0; rep < 4; rep++) {
        const int e4 = tid + rep * (GBLOCKS * 256);
        const int g  = e4 * 4;
        const int hw = g & (HW - 1);
        const int c  = (g >> 10) & (CC - 1);
        const int b  = g >> 18;
        int4   iv = *(const int4*)(g_idx + (b << 10) + hw);
        float4 zv = *(const float4*)(z + g);
        float4 ov;
        ov.x = __ldg(&w[(size_t)iv.x * CC + c]);
        ov.y = __ldg(&w[(size_t)iv.y * CC + c]);
        ov.z = __ldg(&w[(size_t)iv.z * CC + c]);
        ov.w = __ldg(&w[(size_t)iv.w * CC + c]);
        *(float4*)(out + g) = ov;
        float dx = zv.x - ov.x, dy = zv.y - ov.y, dz = zv.z - ov.z, dw = zv.w - ov.w;
        s += (double)dx * dx + (double)dy * dy + (double)dz * dz + (double)dw * dw;
    }
    #pragma unroll
    for (int o = 16; o; o >>= 1) s += __shfl_xor_sync(0xffffffffu, s, o);
    __shared__ double bs[8];
    const int lane = threadIdx.x & 31, wd = threadIdx.x >> 5;
    if (lane == 0) bs[wd] = s;
    __syncthreads();
    if (threadIdx.x == 0) {
        double tot = 0.0;
        #pragma unroll
        for (int i = 0; i < 8; i++) tot += bs[i];
        atomicAdd(&g_loss, tot);
    }
}

__global__ void finalize_kernel(float* __restrict__ out, int out_size) {
    float loss = (float)(g_loss * (1.0 / (double)NQ));
    if (out_size >= NQ + 1) out[NQ] = loss;
    if (out_size >= NQ + 2) out[NQ + 1] = loss;
}

// ---------------------------------------------------------------------------
extern "C" void kernel_launch(void* const* d_in, const int* in_sizes, int n_in,
                              void* d_out, int out_size) {
    const float* z = (const float*)d_in[0];
    const float* w = (const float*)d_in[1];
    float* out = (float*)d_out;

    const int smem = (16384 + 4096 + 1024) * 4;   // 86016 B
    cudaFuncSetAttribute(mma_argmin_kernel,
                         cudaFuncAttributeMaxDynamicSharedMemorySize, smem);

    wnorm_kernel<<<KK / 256, 256>>>(w);
    zn2_kernel<<<NTOT / 256, 256>>>(z);
    wpack_kernel<<<256, 256>>>(w);
    mma_argmin_kernel<<<NTOT / 128, 128, smem>>>(z, w);
    cleanup_kernel<<<256, 256>>>(z, w);
    gather_kernel<<<GBLOCKS, 256>>>(z, w, out);
    finalize_kernel<<<1, 1>>>(out, out_size);
}

// round 12
// speedup vs baseline: 2.5342x; 1.7561x over previous
#include <cuda_runtime.h>
#include <cuda_bf16.h>
#include <cstdint>

// Problem constants
#define BB      32
#define CC      256
#define HW      1024
#define NTOT    32768          // BB*HW
#define KK      1024
#define NQ      8388608        // BB*CC*HW
#define MARGIN  4e-4f

typedef unsigned long long u64;

// Scratch (static device globals only — no runtime alloc)
__device__ double   g_loss;
__device__ int      g_idx[NTOT];
__device__ float    g_wnorm[KK];
__device__ float    g_zn2[NTOT];
__device__ uint32_t g_wpack[131072];     // 1024x256 bf16, fragment-ordered (512KB)
__device__ int      g_cand[NTOT * 8];    // candidate ks for status-1 tokens
__device__ int      g_stat[NTOT];        // 0=done, 1=rescore cands, 2=full scan

// ---------------------------------------------------------------------------
// Kernel 1: ||w_k||^2 — warp per row (coalesced), double reduce
// (order-insensitive: double error ~1e-16 << 3e-5 plateau) + loss init
// ---------------------------------------------------------------------------
__global__ void wnorm_kernel(const float* __restrict__ w) {
    const int k    = blockIdx.x * 8 + (threadIdx.x >> 5);
    const int lane = threadIdx.x & 31;
    if (blockIdx.x == 0 && threadIdx.x == 0) g_loss = 0.0;
    const float* row = w + (size_t)k * CC;
    double s = 0.0;
    #pragma unroll
    for (int i = 0; i < CC / 32; i++) {
        double v = (double)row[lane + i * 32];
        s += v * v;
    }
    #pragma unroll
    for (int o = 16; o; o >>= 1) s += __shfl_xor_sync(0xffffffffu, s, o);
    if (lane == 0) g_wnorm[k] = (float)s;
}

// ---------------------------------------------------------------------------
// Kernel 2: zn2 — exact XLA row-reduce emulation. DO NOT CHANGE (rel_err 0.0).
// ---------------------------------------------------------------------------
__global__ void zn2_kernel(const float* __restrict__ z) {
    const int n  = blockIdx.x * 256 + threadIdx.x;
    const int b  = n >> 10;
    const int hw = n & (HW - 1);
    const float* row = z + (size_t)b * (CC * HW) + hw;
    float W[4];
    #pragma unroll
    for (int w4 = 0; w4 < 4; w4++) {
        float p[32];
        #pragma unroll
        for (int l = 0; l < 32; l++) {
            float a = row[(size_t)(64 * w4 + 2 * l) * HW];
            float c = row[(size_t)(64 * w4 + 2 * l + 1) * HW];
            p[l] = __fadd_rn(__fmul_rn(a, a), __fmul_rn(c, c));
        }
        #pragma unroll
        for (int off = 16; off >= 1; off >>= 1)
            #pragma unroll
            for (int l = 0; l < 16; l++)
                if (l < off) p[l] = __fadd_rn(p[l], p[l + off]);
        W[w4] = p[0];
    }
    g_zn2[n] = __fadd_rn(__fadd_rn(W[0], W[2]), __fadd_rn(W[1], W[3]));
}

// ---------------------------------------------------------------------------
// Kernel 3: pack w into mma B-fragment order (bf16).
// ---------------------------------------------------------------------------
__global__ void wpack_kernel(const float* __restrict__ w) {
    int idx = blockIdx.x * 256 + threadIdx.x;        // 65536 slots
    int t = idx & 31, ks = (idx >> 5) & 15, nb = idx >> 9;
    int code = nb * 8 + (t >> 2);
    int c = t & 3;
    int d0 = ks * 16 + 2 * c;
    const float* wr = w + (size_t)code * CC;
    __nv_bfloat162 r0 = __floats2bfloat162_rn(wr[d0],     wr[d0 + 1]);
    __nv_bfloat162 r1 = __floats2bfloat162_rn(wr[d0 + 8], wr[d0 + 9]);
    g_wpack[idx * 2]     = *(uint32_t*)&r0;
    g_wpack[idx * 2 + 1] = *(uint32_t*)&r1;
}

// ---------------------------------------------------------------------------
// Kernel 4: bf16 mma.sync argmin (unchanged from R11 — proven, 112 us).
// ---------------------------------------------------------------------------
#define UPD(mg, h, s, k) do { \
    if ((s) < v1[mg][h]) { v3[mg][h] = v2[mg][h]; v2[mg][h] = v1[mg][h]; \
        k2[mg][h] = k1[mg][h]; v1[mg][h] = (s); k1[mg][h] = (k); } \
    else if ((s) < v2[mg][h]) { v3[mg][h] = v2[mg][h]; v2[mg][h] = (s); k2[mg][h] = (k); } \
    else if ((s) < v3[mg][h]) { v3[mg][h] = (s); } \
} while (0)

#define MMA_BF16(C, A, b0, b1) \
    asm volatile("mma.sync.aligned.m16n8k16.row.col.f32.bf16.bf16.f32 " \
        "{%0,%1,%2,%3}, {%4,%5,%6,%7}, {%8,%9}, {%0,%1,%2,%3};" \
        : "+f"((C)[0]), "+f"((C)[1]), "+f"((C)[2]), "+f"((C)[3]) \
        : "r"((A).x), "r"((A).y), "r"((A).z), "r"((A).w), "r"(b0), "r"(b1))

__global__ __launch_bounds__(128, 2)
void mma_argmin_kernel(const float* __restrict__ z, const float* __restrict__ w) {
    extern __shared__ uint32_t smu[];
    uint32_t* apack = smu;                        // 16384 u32 (64KB)
    float*    stage = (float*)(smu + 16384);      // 4096 f (16KB)
    float*    wns   = (float*)(smu + 20480);      // 1024 f (4KB)

    const int t = threadIdx.x, wp = t >> 5, lane = t & 31;
    const int c4 = lane & 3;
    const int n0  = blockIdx.x * 128;
    const int b   = blockIdx.x >> 3;
    const int hw0 = (blockIdx.x & 7) * 128;
    const float* zb = z + (size_t)b * (CC * HW) + hw0;

    #pragma unroll
    for (int j = 0; j < 8; j++) wns[j * 128 + t] = g_wnorm[j * 128 + t];

    // ---- pack A (z rows) into fragment-ordered bf16 smem, 32-d chunks ----
    for (int cd = 0; cd < 8; cd++) {
        __syncthreads();
        #pragma unroll
        for (int j = 0; j < 8; j++) {
            int fi = j * 128 + t;
            int dl = fi >> 5, h4 = fi & 31;
            *(float4*)&stage[dl * 128 + h4 * 4] =
                *(const float4*)&zb[(size_t)(cd * 32 + dl) * HW + h4 * 4];
        }
        __syncthreads();
        #pragma unroll
        for (int i = 0; i < 16; i++) {
            int slot = i * 128 + t;
            int ai = slot & 3, tid2 = (slot >> 2) & 31;
            int rp = (slot >> 7) & 1, wp2 = (slot >> 8) & 3, ksl = (slot >> 10) & 1;
            int tok  = wp2 * 32 + rp * 16 + (ai & 1) * 8 + (tid2 >> 2);
            int dloc = ksl * 16 + ((ai >> 1) & 1) * 8 + 2 * (tid2 & 3);
            __nv_bfloat162 v = __floats2bfloat162_rn(stage[dloc * 128 + tok],
                                                     stage[(dloc + 1) * 128 + tok]);
            int ks = cd * 2 + ksl;
            apack[(ks * 8 + wp2 * 2 + rp) * 128 + tid2 * 4 + ai] = *(uint32_t*)&v;
        }
    }
    __syncthreads();

    const uint4* ap4 = (const uint4*)apack;
    const uint2* wpg = (const uint2*)g_wpack;

    float v1[2][2], v2[2][2], v3[2][2];
    int   k1[2][2], k2[2][2];
    #pragma unroll
    for (int a = 0; a < 2; a++)
        #pragma unroll
        for (int h = 0; h < 2; h++) {
            v1[a][h] = v2[a][h] = v3[a][h] = 1e30f;
            k1[a][h] = k2[a][h] = 0x7fffffff;
        }

    for (int nt = 0; nt < 16; nt++) {
        float acc[2][8][4];
        #pragma unroll
        for (int a = 0; a < 2; a++)
            #pragma unroll
            for (int nb = 0; nb < 8; nb++)
                #pragma unroll
                for (int r = 0; r < 4; r++) acc[a][nb][r] = 0.f;

        #pragma unroll
        for (int ks = 0; ks < 16; ks++) {
            uint4 A0 = ap4[(ks * 8 + wp * 2 + 0) * 32 + lane];
            uint4 A1 = ap4[(ks * 8 + wp * 2 + 1) * 32 + lane];
            #pragma unroll
            for (int nb = 0; nb < 8; nb++) {
                uint2 Bv = wpg[((nt * 8 + nb) * 16 + ks) * 32 + lane];
                MMA_BF16(acc[0][nb], A0, Bv.x, Bv.y);
                MMA_BF16(acc[1][nb], A1, Bv.x, Bv.y);
            }
        }
        #pragma unroll
        for (int nb = 0; nb < 8; nb++) {
            int kb = nt * 64 + nb * 8 + 2 * c4;
            float2 wnp = *(const float2*)&wns[kb];
            #pragma unroll
            for (int mg = 0; mg < 2; mg++) {
                float s0 = __fmaf_rn(-2.f, acc[mg][nb][0], wnp.x);
                float s1 = __fmaf_rn(-2.f, acc[mg][nb][1], wnp.y);
                float s2 = __fmaf_rn(-2.f, acc[mg][nb][2], wnp.x);
                float s3 = __fmaf_rn(-2.f, acc[mg][nb][3], wnp.y);
                UPD(mg, 0, s0, kb); UPD(mg, 0, s1, kb + 1);
                UPD(mg, 1, s2, kb); UPD(mg, 1, s3, kb + 1);
            }
        }
    }

    #pragma unroll
    for (int mg = 0; mg < 2; mg++)
        #pragma unroll
        for (int h = 0; h < 2; h++) {
            float gm = v1[mg][h];
            gm = fminf(gm, __shfl_xor_sync(0xffffffffu, gm, 1));
            gm = fminf(gm, __shfl_xor_sync(0xffffffffu, gm, 2));
            float thr = gm + MARGIN;
            int c1 = v1[mg][h] <= thr;
            int c2 = v2[mg][h] <= thr;
            int ov = v3[mg][h] <= thr;
            int tot = c1 + c2;
            tot += __shfl_xor_sync(0xffffffffu, tot, 1);
            tot += __shfl_xor_sync(0xffffffffu, tot, 2);
            ov |= __shfl_xor_sync(0xffffffffu, ov, 1);
            ov |= __shfl_xor_sync(0xffffffffu, ov, 2);
            int kw = c1 ? k1[mg][h] : 0x7fffffff;
            kw = min(kw, __shfl_xor_sync(0xffffffffu, kw, 1));
            kw = min(kw, __shfl_xor_sync(0xffffffffu, kw, 2));
            int n  = n0 + wp * 32 + mg * 16 + h * 8 + (lane >> 2);
            int st = ov ? 2 : (tot == 1 ? 0 : 1);
            if (st == 1) {
                g_cand[n * 8 + c4 * 2]     = c1 ? k1[mg][h] : -1;
                g_cand[n * 8 + c4 * 2 + 1] = c2 ? k2[mg][h] : -1;
            }
            if (c4 == 0) {
                if (st == 0) g_idx[n] = kw;
                g_stat[n] = st;
            }
        }
}

// ---------------------------------------------------------------------------
// Kernel 5: cleanup v2 — tile-staged exact rescore.
// Block = one 128-token tile (same mapping as mma kernel). Stage fp32 z-tile
// into smem [d][tok] (coalesced, conflict-free), early-out if tile certified.
// st=1: thread-per-token serial exact rescore of <=8 candidates.
// st=2: whole block scans all 1024 codes (8/thread) + low-k tie reduce.
// Exact chain: ascending-d fp32 FMA, dist = fl(fl(zn2-2dot)+wn), tie->low k.
// ---------------------------------------------------------------------------
__global__ __launch_bounds__(128, 1)
void cleanup_kernel(const float* __restrict__ z, const float* __restrict__ w) {
    extern __shared__ float zs[];          // [256][128] fp32 = 128KB
    __shared__ int   s2list[128];
    __shared__ int   s2cnt;
    __shared__ float rv[128];
    __shared__ int   rk[128];

    const int t   = threadIdx.x;
    const int n0  = blockIdx.x * 128;
    const int b   = blockIdx.x >> 3;
    const int hw0 = (blockIdx.x & 7) * 128;
    const float* zb = z + (size_t)b * (CC * HW) + hw0;

    if (t == 0) s2cnt = 0;
    const int st = g_stat[n0 + t];
    if (!__syncthreads_or(st != 0)) return;     // whole tile certified

    // stage z tile coalesced: zs[d][tok]
    #pragma unroll
    for (int j = 0; j < 16; j++) {
        int idx = j * 128 + t;                  // 2048 float4 chunks
        int d = idx >> 4, h4 = idx & 15;        // 256 d x 16 h4... 
        // careful: 256*32 float4 = 8192 chunks/4? Recompute: 256 d * 128 tok /4 = 8192 f4.
        (void)d; (void)h4;
    }
    // (correct staging loop below: 8192 float4 chunks, 64 iters of 128 threads)
    #pragma unroll
    for (int j = 0; j < 64; j++) {
        int idx = j * 128 + t;                  // 0..8191
        int d = idx >> 5, h4 = idx & 31;
        *(float4*)&zs[d * 128 + h4 * 4] = *(const float4*)&zb[(size_t)d * HW + h4 * 4];
    }
    __syncthreads();

    const int n = n0 + t;
    if (st == 1) {
        const float zn2v = g_zn2[n];
        float bv = 1e30f; int bk = 0x7fffffff;
        #pragma unroll
        for (int c = 0; c < 8; c++) {
            int k = g_cand[n * 8 + c];
            if (k < 0) continue;
            const float* wr = w + (size_t)k * CC;
            float acc = 0.f;
            #pragma unroll 8
            for (int d = 0; d < CC; d++)
                acc = __fmaf_rn(zs[d * 128 + t], wr[d], acc);
            float d2 = __fadd_rn(__fmaf_rn(-2.f, acc, zn2v), g_wnorm[k]);
            if (d2 < bv || (d2 == bv && k < bk)) { bv = d2; bk = k; }
        }
        g_idx[n] = bk;
    } else if (st == 2) {
        int p = atomicAdd(&s2cnt, 1);
        s2list[p] = t;
    }
    __syncthreads();

    const int cnt = s2cnt;
    for (int i = 0; i < cnt; i++) {
        const int tok = s2list[i];
        const float zn2v = g_zn2[n0 + tok];
        float bv = 1e30f; int bk = 0x7fffffff;
        #pragma unroll
        for (int j = 0; j < 8; j++) {
            int k = t * 8 + j;                   // ascending k per thread
            const float* wr = w + (size_t)k * CC;
            float acc = 0.f;
            #pragma unroll 8
            for (int d = 0; d < CC; d++)
                acc = __fmaf_rn(zs[d * 128 + tok], wr[d], acc);
            float d2 = __fadd_rn(__fmaf_rn(-2.f, acc, zn2v), g_wnorm[k]);
            if (d2 < bv) { bv = d2; bk = k; }
        }
        rv[t] = bv; rk[t] = bk;
        __syncthreads();
        for (int off = 64; off >= 1; off >>= 1) {
            if (t < off) {
                float ov2 = rv[t + off]; int ok2 = rk[t + off];
                if (ov2 < rv[t] || (ov2 == rv[t] && ok2 < rk[t])) {
                    rv[t] = ov2; rk[t] = ok2;
                }
            }
            __syncthreads();
        }
        if (t == 0) g_idx[n0 + tok] = rk[0];
        __syncthreads();
    }
}

// ---------------------------------------------------------------------------
// Kernel 6: gather z_q (float4) + fused MSE; one atomic per block
// ---------------------------------------------------------------------------
#define GBLOCKS 2048
__global__ void gather_kernel(const float* __restrict__ z,
                              const float* __restrict__ w,
                              float* __restrict__ out) {
    const int tid = blockIdx.x * 256 + threadIdx.x;
    double s = 0.0;
    #pragma unroll
    for (int rep = 0; rep < 4; rep++) {
        const int e4 = tid + rep * (GBLOCKS * 256);
        const int g  = e4 * 4;
        const int hw = g & (HW - 1);
        const int c  = (g >> 10) & (CC - 1);
        const int b  = g >> 18;
        int4   iv = *(const int4*)(g_idx + (b << 10) + hw);
        float4 zv = *(const float4*)(z + g);
        float4 ov;
        ov.x = __ldg(&w[(size_t)iv.x * CC + c]);
        ov.y = __ldg(&w[(size_t)iv.y * CC + c]);
        ov.z = __ldg(&w[(size_t)iv.z * CC + c]);
        ov.w = __ldg(&w[(size_t)iv.w * CC + c]);
        *(float4*)(out + g) = ov;
        float dx = zv.x - ov.x, dy = zv.y - ov.y, dz = zv.z - ov.z, dw = zv.w - ov.w;
        s += (double)dx * dx + (double)dy * dy + (double)dz * dz + (double)dw * dw;
    }
    #pragma unroll
    for (int o = 16; o; o >>= 1) s += __shfl_xor_sync(0xffffffffu, s, o);
    __shared__ double bs[8];
    const int lane = threadIdx.x & 31, wd = threadIdx.x >> 5;
    if (lane == 0) bs[wd] = s;
    __syncthreads();
    if (threadIdx.x == 0) {
        double tot = 0.0;
        #pragma unroll
        for (int i = 0; i < 8; i++) tot += bs[i];
        atomicAdd(&g_loss, tot);
    }
}

__global__ void finalize_kernel(float* __restrict__ out, int out_size) {
    float loss = (float)(g_loss * (1.0 / (double)NQ));
    if (out_size >= NQ + 1) out[NQ] = loss;
    if (out_size >= NQ + 2) out[NQ + 1] = loss;
}

// ---------------------------------------------------------------------------
extern "C" void kernel_launch(void* const* d_in, const int* in_sizes, int n_in,
                              void* d_out, int out_size) {
    const float* z = (const float*)d_in[0];
    const float* w = (const float*)d_in[1];
    float* out = (float*)d_out;

    const int smem_mma = (16384 + 4096 + 1024) * 4;   // 86016 B
    const int smem_cln = 256 * 128 * 4;               // 131072 B
    cudaFuncSetAttribute(mma_argmin_kernel,
                         cudaFuncAttributeMaxDynamicSharedMemorySize, smem_mma);
    cudaFuncSetAttribute(cleanup_kernel,
                         cudaFuncAttributeMaxDynamicSharedMemorySize, smem_cln);

    wnorm_kernel<<<KK / 8, 256>>>(w);
    zn2_kernel<<<NTOT / 256, 256>>>(z);
    wpack_kernel<<<256, 256>>>(w);
    mma_argmin_kernel<<<NTOT / 128, 128, smem_mma>>>(z, w);
    cleanup_kernel<<<NTOT / 128, 128, smem_cln>>>(z, w);
    gather_kernel<<<GBLOCKS, 256>>>(z, w, out);
    finalize_kernel<<<1, 1>>>(out, out_size);
}

// round 14
// speedup vs baseline: 2.6631x; 1.0509x over previous
#include <cuda_runtime.h>
#include <cuda_bf16.h>
#include <cstdint>

// Problem constants
#define BB      32
#define CC      256
#define HW      1024
#define NTOT    32768          // BB*HW
#define KK      1024
#define NQ      8388608        // BB*CC*HW
#define MARGIN  4e-4f

typedef unsigned long long u64;

// Scratch (static device globals only — no runtime alloc)
__device__ double   g_loss;
__device__ int      g_idx[NTOT];
__device__ float    g_wnorm[KK];
__device__ float    g_zn2[NTOT];
__device__ uint32_t g_wpack[131072];     // 1024x256 bf16, fragment-ordered (512KB)
__device__ int      g_cand[NTOT * 8];    // candidate ks for status-1 tokens
__device__ int      g_stat[NTOT];        // 0=done, 1=rescore cands, 2=full scan

// ---------------------------------------------------------------------------
// Kernel 1: ||w_k||^2 — warp per row (coalesced), double reduce + loss init
// ---------------------------------------------------------------------------
__global__ void wnorm_kernel(const float* __restrict__ w) {
    const int k    = blockIdx.x * 8 + (threadIdx.x >> 5);
    const int lane = threadIdx.x & 31;
    if (blockIdx.x == 0 && threadIdx.x == 0) g_loss = 0.0;
    const float* row = w + (size_t)k * CC;
    double s = 0.0;
    #pragma unroll
    for (int i = 0; i < CC / 32; i++) {
        double v = (double)row[lane + i * 32];
        s += v * v;
    }
    #pragma unroll
    for (int o = 16; o; o >>= 1) s += __shfl_xor_sync(0xffffffffu, s, o);
    if (lane == 0) g_wnorm[k] = (float)s;
}

// ---------------------------------------------------------------------------
// Kernel 2: zn2 — exact XLA row-reduce emulation. DO NOT CHANGE (rel_err 0.0).
// ---------------------------------------------------------------------------
__global__ void zn2_kernel(const float* __restrict__ z) {
    const int n  = blockIdx.x * 256 + threadIdx.x;
    const int b  = n >> 10;
    const int hw = n & (HW - 1);
    const float* row = z + (size_t)b * (CC * HW) + hw;
    float W[4];
    #pragma unroll
    for (int w4 = 0; w4 < 4; w4++) {
        float p[32];
        #pragma unroll
        for (int l = 0; l < 32; l++) {
            float a = row[(size_t)(64 * w4 + 2 * l) * HW];
            float c = row[(size_t)(64 * w4 + 2 * l + 1) * HW];
            p[l] = __fadd_rn(__fmul_rn(a, a), __fmul_rn(c, c));
        }
        #pragma unroll
        for (int off = 16; off >= 1; off >>= 1)
            #pragma unroll
            for (int l = 0; l < 16; l++)
                if (l < off) p[l] = __fadd_rn(p[l], p[l + off]);
        W[w4] = p[0];
    }
    g_zn2[n] = __fadd_rn(__fadd_rn(W[0], W[2]), __fadd_rn(W[1], W[3]));
}

// ---------------------------------------------------------------------------
// Kernel 3: pack w into mma B-fragment order (bf16).
// ---------------------------------------------------------------------------
__global__ void wpack_kernel(const float* __restrict__ w) {
    int idx = blockIdx.x * 256 + threadIdx.x;        // 65536 slots
    int t = idx & 31, ks = (idx >> 5) & 15, nb = idx >> 9;
    int code = nb * 8 + (t >> 2);
    int c = t & 3;
    int d0 = ks * 16 + 2 * c;
    const float* wr = w + (size_t)code * CC;
    __nv_bfloat162 r0 = __floats2bfloat162_rn(wr[d0],     wr[d0 + 1]);
    __nv_bfloat162 r1 = __floats2bfloat162_rn(wr[d0 + 8], wr[d0 + 9]);
    g_wpack[idx * 2]     = *(uint32_t*)&r0;
    g_wpack[idx * 2 + 1] = *(uint32_t*)&r1;
}

// ---------------------------------------------------------------------------
// Kernel 4: bf16 mma.sync argmin (unchanged — proven, 112 us, rel_err 0.0).
// ---------------------------------------------------------------------------
#define UPD(mg, h, s, k) do { \
    if ((s) < v1[mg][h]) { v3[mg][h] = v2[mg][h]; v2[mg][h] = v1[mg][h]; \
        k2[mg][h] = k1[mg][h]; v1[mg][h] = (s); k1[mg][h] = (k); } \
    else if ((s) < v2[mg][h]) { v3[mg][h] = v2[mg][h]; v2[mg][h] = (s); k2[mg][h] = (k); } \
    else if ((s) < v3[mg][h]) { v3[mg][h] = (s); } \
} while (0)

#define MMA_BF16(C, A, b0, b1) \
    asm volatile("mma.sync.aligned.m16n8k16.row.col.f32.bf16.bf16.f32 " \
        "{%0,%1,%2,%3}, {%4,%5,%6,%7}, {%8,%9}, {%0,%1,%2,%3};" \
        : "+f"((C)[0]), "+f"((C)[1]), "+f"((C)[2]), "+f"((C)[3]) \
        : "r"((A).x), "r"((A).y), "r"((A).z), "r"((A).w), "r"(b0), "r"(b1))

__global__ __launch_bounds__(128, 2)
void mma_argmin_kernel(const float* __restrict__ z, const float* __restrict__ w) {
    extern __shared__ uint32_t smu[];
    uint32_t* apack = smu;                        // 16384 u32 (64KB)
    float*    stage = (float*)(smu + 16384);      // 4096 f (16KB)
    float*    wns   = (float*)(smu + 20480);      // 1024 f (4KB)

    const int t = threadIdx.x, wp = t >> 5, lane = t & 31;
    const int c4 = lane & 3;
    const int n0  = blockIdx.x * 128;
    const int b   = blockIdx.x >> 3;
    const int hw0 = (blockIdx.x & 7) * 128;
    const float* zb = z + (size_t)b * (CC * HW) + hw0;

    #pragma unroll
    for (int j = 0; j < 8; j++) wns[j * 128 + t] = g_wnorm[j * 128 + t];

    for (int cd = 0; cd < 8; cd++) {
        __syncthreads();
        #pragma unroll
        for (int j = 0; j < 8; j++) {
            int fi = j * 128 + t;
            int dl = fi >> 5, h4 = fi & 31;
            *(float4*)&stage[dl * 128 + h4 * 4] =
                *(const float4*)&zb[(size_t)(cd * 32 + dl) * HW + h4 * 4];
        }
        __syncthreads();
        #pragma unroll
        for (int i = 0; i < 16; i++) {
            int slot = i * 128 + t;
            int ai = slot & 3, tid2 = (slot >> 2) & 31;
            int rp = (slot >> 7) & 1, wp2 = (slot >> 8) & 3, ksl = (slot >> 10) & 1;
            int tok  = wp2 * 32 + rp * 16 + (ai & 1) * 8 + (tid2 >> 2);
            int dloc = ksl * 16 + ((ai >> 1) & 1) * 8 + 2 * (tid2 & 3);
            __nv_bfloat162 v = __floats2bfloat162_rn(stage[dloc * 128 + tok],
                                                     stage[(dloc + 1) * 128 + tok]);
            int ks = cd * 2 + ksl;
            apack[(ks * 8 + wp2 * 2 + rp) * 128 + tid2 * 4 + ai] = *(uint32_t*)&v;
        }
    }
    __syncthreads();

    const uint4* ap4 = (const uint4*)apack;
    const uint2* wpg = (const uint2*)g_wpack;

    float v1[2][2], v2[2][2], v3[2][2];
    int   k1[2][2], k2[2][2];
    #pragma unroll
    for (int a = 0; a < 2; a++)
        #pragma unroll
        for (int h = 0; h < 2; h++) {
            v1[a][h] = v2[a][h] = v3[a][h] = 1e30f;
            k1[a][h] = k2[a][h] = 0x7fffffff;
        }

    for (int nt = 0; nt < 16; nt++) {
        float acc[2][8][4];
        #pragma unroll
        for (int a = 0; a < 2; a++)
            #pragma unroll
            for (int nb = 0; nb < 8; nb++)
                #pragma unroll
                for (int r = 0; r < 4; r++) acc[a][nb][r] = 0.f;

        #pragma unroll
        for (int ks = 0; ks < 16; ks++) {
            uint4 A0 = ap4[(ks * 8 + wp * 2 + 0) * 32 + lane];
            uint4 A1 = ap4[(ks * 8 + wp * 2 + 1) * 32 + lane];
            #pragma unroll
            for (int nb = 0; nb < 8; nb++) {
                uint2 Bv = wpg[((nt * 8 + nb) * 16 + ks) * 32 + lane];
                MMA_BF16(acc[0][nb], A0, Bv.x, Bv.y);
                MMA_BF16(acc[1][nb], A1, Bv.x, Bv.y);
            }
        }
        #pragma unroll
        for (int nb = 0; nb < 8; nb++) {
            int kb = nt * 64 + nb * 8 + 2 * c4;
            float2 wnp = *(const float2*)&wns[kb];
            #pragma unroll
            for (int mg = 0; mg < 2; mg++) {
                float s0 = __fmaf_rn(-2.f, acc[mg][nb][0], wnp.x);
                float s1 = __fmaf_rn(-2.f, acc[mg][nb][1], wnp.y);
                float s2 = __fmaf_rn(-2.f, acc[mg][nb][2], wnp.x);
                float s3 = __fmaf_rn(-2.f, acc[mg][nb][3], wnp.y);
                UPD(mg, 0, s0, kb); UPD(mg, 0, s1, kb + 1);
                UPD(mg, 1, s2, kb); UPD(mg, 1, s3, kb + 1);
            }
        }
    }

    #pragma unroll
    for (int mg = 0; mg < 2; mg++)
        #pragma unroll
        for (int h = 0; h < 2; h++) {
            float gm = v1[mg][h];
            gm = fminf(gm, __shfl_xor_sync(0xffffffffu, gm, 1));
            gm = fminf(gm, __shfl_xor_sync(0xffffffffu, gm, 2));
            float thr = gm + MARGIN;
            int c1 = v1[mg][h] <= thr;
            int c2 = v2[mg][h] <= thr;
            int ov = v3[mg][h] <= thr;
            int tot = c1 + c2;
            tot += __shfl_xor_sync(0xffffffffu, tot, 1);
            tot += __shfl_xor_sync(0xffffffffu, tot, 2);
            ov |= __shfl_xor_sync(0xffffffffu, ov, 1);
            ov |= __shfl_xor_sync(0xffffffffu, ov, 2);
            int kw = c1 ? k1[mg][h] : 0x7fffffff;
            kw = min(kw, __shfl_xor_sync(0xffffffffu, kw, 1));
            kw = min(kw, __shfl_xor_sync(0xffffffffu, kw, 2));
            int n  = n0 + wp * 32 + mg * 16 + h * 8 + (lane >> 2);
            int st = ov ? 2 : (tot == 1 ? 0 : 1);
            if (st == 1) {
                g_cand[n * 8 + c4 * 2]     = c1 ? k1[mg][h] : -1;
                g_cand[n * 8 + c4 * 2 + 1] = c2 ? k2[mg][h] : -1;
            }
            if (c4 == 0) {
                if (st == 0) g_idx[n] = kw;
                g_stat[n] = st;
            }
        }
}

// ---------------------------------------------------------------------------
// Kernel 5: cleanup v3 — tile-staged exact rescore, float4 w reads.
// Exact chain preserved: float4 load then 4 sequential ascending-d FMAs is
// the identical operation order as scalar loads.
// ---------------------------------------------------------------------------
__global__ __launch_bounds__(128, 1)
void cleanup_kernel(const float* __restrict__ z, const float* __restrict__ w) {
    extern __shared__ float zs[];          // [256][128] fp32 = 128KB
    __shared__ int   s2list[128];
    __shared__ int   s2cnt;
    __shared__ float rv[128];
    __shared__ int   rk[128];

    const int t   = threadIdx.x;
    const int n0  = blockIdx.x * 128;
    const int b   = blockIdx.x >> 3;
    const int hw0 = (blockIdx.x & 7) * 128;
    const float* zb = z + (size_t)b * (CC * HW) + hw0;

    if (t == 0) s2cnt = 0;
    const int st = g_stat[n0 + t];
    if (!__syncthreads_or(st != 0)) return;     // whole tile certified

    // stage z tile coalesced: zs[d][tok]
    #pragma unroll
    for (int j = 0; j < 64; j++) {
        int idx = j * 128 + t;                  // 0..8191 float4 chunks
        int d = idx >> 5, h4 = idx & 31;
        *(float4*)&zs[d * 128 + h4 * 4] = *(const float4*)&zb[(size_t)d * HW + h4 * 4];
    }
    __syncthreads();

    const int n = n0 + t;
    if (st == 1) {
        const float zn2v = g_zn2[n];
        float bv = 1e30f; int bk = 0x7fffffff;
        #pragma unroll
        for (int c = 0; c < 8; c++) {
            int k = g_cand[n * 8 + c];
            if (k < 0) continue;
            const float4* wr4 = (const float4*)(w + (size_t)k * CC);
            float acc = 0.f;
            #pragma unroll 16
            for (int i = 0; i < CC / 4; i++) {
                float4 v = __ldg(&wr4[i]);
                acc = __fmaf_rn(zs[(4 * i + 0) * 128 + t], v.x, acc);
                acc = __fmaf_rn(zs[(4 * i + 1) * 128 + t], v.y, acc);
                acc = __fmaf_rn(zs[(4 * i + 2) * 128 + t], v.z, acc);
                acc = __fmaf_rn(zs[(4 * i + 3) * 128 + t], v.w, acc);
            }
            float d2 = __fadd_rn(__fmaf_rn(-2.f, acc, zn2v), g_wnorm[k]);
            if (d2 < bv || (d2 == bv && k < bk)) { bv = d2; bk = k; }
        }
        g_idx[n] = bk;
    } else if (st == 2) {
        int p = atomicAdd(&s2cnt, 1);
        s2list[p] = t;
    }
    __syncthreads();

    const int cnt = s2cnt;
    for (int i = 0; i < cnt; i++) {
        const int tok = s2list[i];
        const float zn2v = g_zn2[n0 + tok];
        float bv = 1e30f; int bk = 0x7fffffff;
        #pragma unroll
        for (int j = 0; j < 8; j++) {
            int k = t * 8 + j;                   // ascending k per thread
            const float4* wr4 = (const float4*)(w + (size_t)k * CC);
            float acc = 0.f;
            #pragma unroll 16
            for (int i2 = 0; i2 < CC / 4; i2++) {
                float4 v = __ldg(&wr4[i2]);
                acc = __fmaf_rn(zs[(4 * i2 + 0) * 128 + tok], v.x, acc);
                acc = __fmaf_rn(zs[(4 * i2 + 1) * 128 + tok], v.y, acc);
                acc = __fmaf_rn(zs[(4 * i2 + 2) * 128 + tok], v.z, acc);
                acc = __fmaf_rn(zs[(4 * i2 + 3) * 128 + tok], v.w, acc);
            }
            float d2 = __fadd_rn(__fmaf_rn(-2.f, acc, zn2v), g_wnorm[k]);
            if (d2 < bv) { bv = d2; bk = k; }
        }
        rv[t] = bv; rk[t] = bk;
        __syncthreads();
        for (int off = 64; off >= 1; off >>= 1) {
            if (t < off) {
                float ov2 = rv[t + off]; int ok2 = rk[t + off];
                if (ov2 < rv[t] || (ov2 == rv[t] && ok2 < rk[t])) {
                    rv[t] = ov2; rk[t] = ok2;
                }
            }
            __syncthreads();
        }
        if (t == 0) g_idx[n0 + tok] = rk[0];
        __syncthreads();
    }
}

// ---------------------------------------------------------------------------
// Kernel 6: gather v2 — tile-staged. Block = 64 tokens, 256 threads.
// Stage the 64 selected w rows in smem (coalesced float4 global reads,
// SCALAR smem stores — row stride 257 is not 16B aligned), then emit
// out[b][c][hw-tile] with coalesced 128B writes; fused MSE, 1 atomic/block.
// smem: wstg[64][257] floats (stride 257 => conflict-free tok-major reads)
// ---------------------------------------------------------------------------
__global__ __launch_bounds__(256, 1)
void gather_kernel(const float* __restrict__ z,
                   const float* __restrict__ w,
                   float* __restrict__ out) {
    extern __shared__ float wstg[];               // 64*257 floats
    const int t   = threadIdx.x;
    const int n0  = blockIdx.x * 64;              // 512 blocks
    const int b   = n0 >> 10;
    const int hw0 = n0 & (HW - 1);

    // stage 64 w rows: warp wp handles rows wp*8..wp*8+7; 64 f4 per row
    {
        const int wp = t >> 5, lane = t & 31;
        #pragma unroll
        for (int r = 0; r < 8; r++) {
            const int tok = wp * 8 + r;
            const int k = g_idx[n0 + tok];
            const float4* src = (const float4*)(w + (size_t)k * CC);
            #pragma unroll
            for (int j = 0; j < 2; j++) {
                const int i = lane + j * 32;      // 0..63 f4
                float4 v = __ldg(&src[i]);
                float* dst = &wstg[tok * 257 + i * 4];
                dst[0] = v.x; dst[1] = v.y; dst[2] = v.z; dst[3] = v.w;
            }
        }
    }
    __syncthreads();

    // emit: thread t -> tok = t&63, c-quarter = t>>6
    const int tok = t & 63;
    const int cq  = t >> 6;
    double s = 0.0;
    #pragma unroll 16
    for (int cc = 0; cc < 64; cc++) {
        const int c = cq * 64 + cc;
        const size_t g = ((size_t)b * CC + c) * HW + hw0 + tok;
        const float v = wstg[tok * 257 + c];
        const float zv = z[g];
        out[g] = v;
        const float d = zv - v;
        s += (double)d * (double)d;
    }
    #pragma unroll
    for (int o = 16; o; o >>= 1) s += __shfl_xor_sync(0xffffffffu, s, o);
    __shared__ double bs[8];
    const int lane = t & 31, wd = t >> 5;
    if (lane == 0) bs[wd] = s;
    __syncthreads();
    if (t == 0) {
        double tot = 0.0;
        #pragma unroll
        for (int i = 0; i < 8; i++) tot += bs[i];
        atomicAdd(&g_loss, tot);
    }
}

__global__ void finalize_kernel(float* __restrict__ out, int out_size) {
    float loss = (float)(g_loss * (1.0 / (double)NQ));
    if (out_size >= NQ + 1) out[NQ] = loss;
    if (out_size >= NQ + 2) out[NQ + 1] = loss;
}

// ---------------------------------------------------------------------------
extern "C" void kernel_launch(void* const* d_in, const int* in_sizes, int n_in,
                              void* d_out, int out_size) {
    const float* z = (const float*)d_in[0];
    const float* w = (const float*)d_in[1];
    float* out = (float*)d_out;

    const int smem_mma = (16384 + 4096 + 1024) * 4;   // 86016 B
    const int smem_cln = 256 * 128 * 4;               // 131072 B
    const int smem_gth = 64 * 257 * 4;                // 65792 B
    cudaFuncSetAttribute(mma_argmin_kernel,
                         cudaFuncAttributeMaxDynamicSharedMemorySize, smem_mma);
    cudaFuncSetAttribute(cleanup_kernel,
                         cudaFuncAttributeMaxDynamicSharedMemorySize, smem_cln);
    cudaFuncSetAttribute(gather_kernel,
                         cudaFuncAttributeMaxDynamicSharedMemorySize, smem_gth);

    wnorm_kernel<<<KK / 8, 256>>>(w);
    zn2_kernel<<<NTOT / 256, 256>>>(z);
    wpack_kernel<<<256, 256>>>(w);
    mma_argmin_kernel<<<NTOT / 128, 128, smem_mma>>>(z, w);
    cleanup_kernel<<<NTOT / 128, 128, smem_cln>>>(z, w);
    gather_kernel<<<NTOT / 64, 256, smem_gth>>>(z, w, out);
    finalize_kernel<<<1, 1>>>(out, out_size);
}

// round 15
// speedup vs baseline: 4.2508x; 1.5962x over previous
#include <cuda_runtime.h>
#include <cuda_bf16.h>
#include <cstdint>

// Problem constants
#define BB      32
#define CC      256
#define HW      1024
#define NTOT    32768          // BB*HW
#define KK      1024
#define NQ      8388608        // BB*CC*HW
#define MARGIN  4e-4f

typedef unsigned long long u64;

// Scratch (static device globals only — no runtime alloc)
__device__ double   g_loss;
__device__ int      g_idx[NTOT];
__device__ float    g_wnorm[KK];
__device__ float    g_zn2[NTOT];
__device__ uint32_t g_wpack[131072];     // 1024x256 bf16, fragment-ordered (512KB)
__device__ int      g_cand[NTOT * 8];    // candidate ks for status-1 tokens
__device__ int      g_stat[NTOT];        // 0=done, 1=rescore cands, 2=full scan

// ---------------------------------------------------------------------------
// Kernel 1: ||w_k||^2 — warp per row (coalesced), double reduce + loss init
// ---------------------------------------------------------------------------
__global__ void wnorm_kernel(const float* __restrict__ w) {
    const int k    = blockIdx.x * 8 + (threadIdx.x >> 5);
    const int lane = threadIdx.x & 31;
    if (blockIdx.x == 0 && threadIdx.x == 0) g_loss = 0.0;
    const float* row = w + (size_t)k * CC;
    double s = 0.0;
    #pragma unroll
    for (int i = 0; i < CC / 32; i++) {
        double v = (double)row[lane + i * 32];
        s += v * v;
    }
    #pragma unroll
    for (int o = 16; o; o >>= 1) s += __shfl_xor_sync(0xffffffffu, s, o);
    if (lane == 0) g_wnorm[k] = (float)s;
}

// ---------------------------------------------------------------------------
// Kernel 2: zn2 — exact XLA row-reduce emulation. DO NOT CHANGE (rel_err 0.0).
// ---------------------------------------------------------------------------
__global__ void zn2_kernel(const float* __restrict__ z) {
    const int n  = blockIdx.x * 256 + threadIdx.x;
    const int b  = n >> 10;
    const int hw = n & (HW - 1);
    const float* row = z + (size_t)b * (CC * HW) + hw;
    float W[4];
    #pragma unroll
    for (int w4 = 0; w4 < 4; w4++) {
        float p[32];
        #pragma unroll
        for (int l = 0; l < 32; l++) {
            float a = row[(size_t)(64 * w4 + 2 * l) * HW];
            float c = row[(size_t)(64 * w4 + 2 * l + 1) * HW];
            p[l] = __fadd_rn(__fmul_rn(a, a), __fmul_rn(c, c));
        }
        #pragma unroll
        for (int off = 16; off >= 1; off >>= 1)
            #pragma unroll
            for (int l = 0; l < 16; l++)
                if (l < off) p[l] = __fadd_rn(p[l], p[l + off]);
        W[w4] = p[0];
    }
    g_zn2[n] = __fadd_rn(__fadd_rn(W[0], W[2]), __fadd_rn(W[1], W[3]));
}

// ---------------------------------------------------------------------------
// Kernel 3: pack w into mma B-fragment order (bf16).
// ---------------------------------------------------------------------------
__global__ void wpack_kernel(const float* __restrict__ w) {
    int idx = blockIdx.x * 256 + threadIdx.x;        // 65536 slots
    int t = idx & 31, ks = (idx >> 5) & 15, nb = idx >> 9;
    int code = nb * 8 + (t >> 2);
    int c = t & 3;
    int d0 = ks * 16 + 2 * c;
    const float* wr = w + (size_t)code * CC;
    __nv_bfloat162 r0 = __floats2bfloat162_rn(wr[d0],     wr[d0 + 1]);
    __nv_bfloat162 r1 = __floats2bfloat162_rn(wr[d0 + 8], wr[d0 + 9]);
    g_wpack[idx * 2]     = *(uint32_t*)&r0;
    g_wpack[idx * 2 + 1] = *(uint32_t*)&r1;
}

// ---------------------------------------------------------------------------
// Kernel 4: bf16 mma.sync argmin v2 — 256 threads / 8 warps, 16 tokens/warp,
// software-pipelined A/B fragment prefetch. Same apack layout & certify logic.
// ---------------------------------------------------------------------------
#define UPD(h, s, k) do { \
    if ((s) < v1[h]) { v3[h] = v2[h]; v2[h] = v1[h]; k2[h] = k1[h]; \
        v1[h] = (s); k1[h] = (k); } \
    else if ((s) < v2[h]) { v3[h] = v2[h]; v2[h] = (s); k2[h] = (k); } \
    else if ((s) < v3[h]) { v3[h] = (s); } \
} while (0)

#define MMA_BF16(C, A, b0, b1) \
    asm volatile("mma.sync.aligned.m16n8k16.row.col.f32.bf16.bf16.f32 " \
        "{%0,%1,%2,%3}, {%4,%5,%6,%7}, {%8,%9}, {%0,%1,%2,%3};" \
        : "+f"((C)[0]), "+f"((C)[1]), "+f"((C)[2]), "+f"((C)[3]) \
        : "r"((A).x), "r"((A).y), "r"((A).z), "r"((A).w), "r"(b0), "r"(b1))

__global__ __launch_bounds__(256, 2)
void mma_argmin_kernel(const float* __restrict__ z, const float* __restrict__ w) {
    extern __shared__ uint32_t smu[];
    uint32_t* apack = smu;                        // 16384 u32 (64KB)
    float*    stage = (float*)(smu + 16384);      // 4096 f (16KB)
    float*    wns   = (float*)(smu + 20480);      // 1024 f (4KB)

    const int t = threadIdx.x, wp = t >> 5, lane = t & 31;
    const int c4 = lane & 3;
    const int n0  = blockIdx.x * 128;
    const int b   = blockIdx.x >> 3;
    const int hw0 = (blockIdx.x & 7) * 128;
    const float* zb = z + (size_t)b * (CC * HW) + hw0;

    #pragma unroll
    for (int j = 0; j < 4; j++) wns[j * 256 + t] = g_wnorm[j * 256 + t];

    // ---- pack A (z rows) into fragment-ordered bf16 smem, 32-d chunks ----
    for (int cd = 0; cd < 8; cd++) {
        __syncthreads();
        #pragma unroll
        for (int j = 0; j < 4; j++) {
            int fi = j * 256 + t;                 // 1024 float4 chunks
            int dl = fi >> 5, h4 = fi & 31;
            *(float4*)&stage[dl * 128 + h4 * 4] =
                *(const float4*)&zb[(size_t)(cd * 32 + dl) * HW + h4 * 4];
        }
        __syncthreads();
        #pragma unroll
        for (int i = 0; i < 8; i++) {
            int slot = i * 256 + t;               // 2048 slots
            int ai = slot & 3, tid2 = (slot >> 2) & 31;
            int rp = (slot >> 7) & 1, wp2 = (slot >> 8) & 3, ksl = (slot >> 10) & 1;
            int tok  = wp2 * 32 + rp * 16 + (ai & 1) * 8 + (tid2 >> 2);
            int dloc = ksl * 16 + ((ai >> 1) & 1) * 8 + 2 * (tid2 & 3);
            __nv_bfloat162 v = __floats2bfloat162_rn(stage[dloc * 128 + tok],
                                                     stage[(dloc + 1) * 128 + tok]);
            int ks = cd * 2 + ksl;
            apack[(ks * 8 + wp2 * 2 + rp) * 128 + tid2 * 4 + ai] = *(uint32_t*)&v;
        }
    }
    __syncthreads();

    const uint4* ap4 = (const uint4*)apack;
    const uint2* wpg = (const uint2*)g_wpack;

    float v1[2], v2[2], v3[2];
    int   k1[2], k2[2];
    #pragma unroll
    for (int h = 0; h < 2; h++) {
        v1[h] = v2[h] = v3[h] = 1e30f;
        k1[h] = k2[h] = 0x7fffffff;
    }

    for (int nt = 0; nt < 16; nt++) {
        float acc[8][4];
        #pragma unroll
        for (int nb = 0; nb < 8; nb++)
            #pragma unroll
            for (int r = 0; r < 4; r++) acc[nb][r] = 0.f;

        // software pipeline: prefetch ks+1 fragments while issuing ks MMAs
        uint4 A = ap4[(0 * 8 + wp) * 32 + lane];
        uint2 Bv[8];
        #pragma unroll
        for (int nb = 0; nb < 8; nb++)
            Bv[nb] = wpg[((nt * 8 + nb) * 16 + 0) * 32 + lane];

        #pragma unroll
        for (int ks = 0; ks < 16; ks++) {
            uint4 An;
            uint2 Bn[8];
            if (ks < 15) {
                An = ap4[((ks + 1) * 8 + wp) * 32 + lane];
                #pragma unroll
                for (int nb = 0; nb < 8; nb++)
                    Bn[nb] = wpg[((nt * 8 + nb) * 16 + ks + 1) * 32 + lane];
            }
            #pragma unroll
            for (int nb = 0; nb < 8; nb++)
                MMA_BF16(acc[nb], A, Bv[nb].x, Bv[nb].y);
            if (ks < 15) {
                A = An;
                #pragma unroll
                for (int nb = 0; nb < 8; nb++) Bv[nb] = Bn[nb];
            }
        }

        // epilogue: s = wn - 2*dot; per-thread top-2(+3rd) tracking
        #pragma unroll
        for (int nb = 0; nb < 8; nb++) {
            int kb = nt * 64 + nb * 8 + 2 * c4;
            float2 wnp = *(const float2*)&wns[kb];
            float s0 = __fmaf_rn(-2.f, acc[nb][0], wnp.x);
            float s1 = __fmaf_rn(-2.f, acc[nb][1], wnp.y);
            float s2 = __fmaf_rn(-2.f, acc[nb][2], wnp.x);
            float s3 = __fmaf_rn(-2.f, acc[nb][3], wnp.y);
            UPD(0, s0, kb); UPD(0, s1, kb + 1);
            UPD(1, s2, kb); UPD(1, s3, kb + 1);
        }
    }

    // ---- per token-row: quad-combine, certify or hand off ----
    #pragma unroll
    for (int h = 0; h < 2; h++) {
        float gm = v1[h];
        gm = fminf(gm, __shfl_xor_sync(0xffffffffu, gm, 1));
        gm = fminf(gm, __shfl_xor_sync(0xffffffffu, gm, 2));
        float thr = gm + MARGIN;
        int c1 = v1[h] <= thr;
        int c2 = v2[h] <= thr;
        int ov = v3[h] <= thr;
        int tot = c1 + c2;
        tot += __shfl_xor_sync(0xffffffffu, tot, 1);
        tot += __shfl_xor_sync(0xffffffffu, tot, 2);
        ov |= __shfl_xor_sync(0xffffffffu, ov, 1);
        ov |= __shfl_xor_sync(0xffffffffu, ov, 2);
        int kw = c1 ? k1[h] : 0x7fffffff;
        kw = min(kw, __shfl_xor_sync(0xffffffffu, kw, 1));
        kw = min(kw, __shfl_xor_sync(0xffffffffu, kw, 2));
        int n  = n0 + wp * 16 + h * 8 + (lane >> 2);
        int st = ov ? 2 : (tot == 1 ? 0 : 1);
        if (st == 1) {
            g_cand[n * 8 + c4 * 2]     = c1 ? k1[h] : -1;
            g_cand[n * 8 + c4 * 2 + 1] = c2 ? k2[h] : -1;
        }
        if (c4 == 0) {
            if (st == 0) g_idx[n] = kw;
            g_stat[n] = st;
        }
    }
}

// ---------------------------------------------------------------------------
// Kernel 5: cleanup v3 — tile-staged exact rescore, float4 w reads.
// Exact chain preserved: float4 load then 4 sequential ascending-d FMAs is
// the identical operation order as scalar loads.
// ---------------------------------------------------------------------------
__global__ __launch_bounds__(128, 1)
void cleanup_kernel(const float* __restrict__ z, const float* __restrict__ w) {
    extern __shared__ float zs[];          // [256][128] fp32 = 128KB
    __shared__ int   s2list[128];
    __shared__ int   s2cnt;
    __shared__ float rv[128];
    __shared__ int   rk[128];

    const int t   = threadIdx.x;
    const int n0  = blockIdx.x * 128;
    const int b   = blockIdx.x >> 3;
    const int hw0 = (blockIdx.x & 7) * 128;
    const float* zb = z + (size_t)b * (CC * HW) + hw0;

    if (t == 0) s2cnt = 0;
    const int st = g_stat[n0 + t];
    if (!__syncthreads_or(st != 0)) return;     // whole tile certified

    // stage z tile coalesced: zs[d][tok]
    #pragma unroll
    for (int j = 0; j < 64; j++) {
        int idx = j * 128 + t;                  // 0..8191 float4 chunks
        int d = idx >> 5, h4 = idx & 31;
        *(float4*)&zs[d * 128 + h4 * 4] = *(const float4*)&zb[(size_t)d * HW + h4 * 4];
    }
    __syncthreads();

    const int n = n0 + t;
    if (st == 1) {
        const float zn2v = g_zn2[n];
        float bv = 1e30f; int bk = 0x7fffffff;
        #pragma unroll
        for (int c = 0; c < 8; c++) {
            int k = g_cand[n * 8 + c];
            if (k < 0) continue;
            const float4* wr4 = (const float4*)(w + (size_t)k * CC);
            float acc = 0.f;
            #pragma unroll 16
            for (int i = 0; i < CC / 4; i++) {
                float4 v = __ldg(&wr4[i]);
                acc = __fmaf_rn(zs[(4 * i + 0) * 128 + t], v.x, acc);
                acc = __fmaf_rn(zs[(4 * i + 1) * 128 + t], v.y, acc);
                acc = __fmaf_rn(zs[(4 * i + 2) * 128 + t], v.z, acc);
                acc = __fmaf_rn(zs[(4 * i + 3) * 128 + t], v.w, acc);
            }
            float d2 = __fadd_rn(__fmaf_rn(-2.f, acc, zn2v), g_wnorm[k]);
            if (d2 < bv || (d2 == bv && k < bk)) { bv = d2; bk = k; }
        }
        g_idx[n] = bk;
    } else if (st == 2) {
        int p = atomicAdd(&s2cnt, 1);
        s2list[p] = t;
    }
    __syncthreads();

    const int cnt = s2cnt;
    for (int i = 0; i < cnt; i++) {
        const int tok = s2list[i];
        const float zn2v = g_zn2[n0 + tok];
        float bv = 1e30f; int bk = 0x7fffffff;
        #pragma unroll
        for (int j = 0; j < 8; j++) {
            int k = t * 8 + j;                   // ascending k per thread
            const float4* wr4 = (const float4*)(w + (size_t)k * CC);
            float acc = 0.f;
            #pragma unroll 16
            for (int i2 = 0; i2 < CC / 4; i2++) {
                float4 v = __ldg(&wr4[i2]);
                acc = __fmaf_rn(zs[(4 * i2 + 0) * 128 + tok], v.x, acc);
                acc = __fmaf_rn(zs[(4 * i2 + 1) * 128 + tok], v.y, acc);
                acc = __fmaf_rn(zs[(4 * i2 + 2) * 128 + tok], v.z, acc);
                acc = __fmaf_rn(zs[(4 * i2 + 3) * 128 + tok], v.w, acc);
            }
            float d2 = __fadd_rn(__fmaf_rn(-2.f, acc, zn2v), g_wnorm[k]);
            if (d2 < bv) { bv = d2; bk = k; }
        }
        rv[t] = bv; rk[t] = bk;
        __syncthreads();
        for (int off = 64; off >= 1; off >>= 1) {
            if (t < off) {
                float ov2 = rv[t + off]; int ok2 = rk[t + off];
                if (ov2 < rv[t] || (ov2 == rv[t] && ok2 < rk[t])) {
                    rv[t] = ov2; rk[t] = ok2;
                }
            }
            __syncthreads();
        }
        if (t == 0) g_idx[n0 + tok] = rk[0];
        __syncthreads();
    }
}

// ---------------------------------------------------------------------------
// Kernel 6: gather v2 — tile-staged. Block = 64 tokens, 256 threads.
// ---------------------------------------------------------------------------
__global__ __launch_bounds__(256, 1)
void gather_kernel(const float* __restrict__ z,
                   const float* __restrict__ w,
                   float* __restrict__ out) {
    extern __shared__ float wstg[];               // 64*257 floats
    const int t   = threadIdx.x;
    const int n0  = blockIdx.x * 64;              // 512 blocks
    const int b   = n0 >> 10;
    const int hw0 = n0 & (HW - 1);

    {
        const int wp = t >> 5, lane = t & 31;
        #pragma unroll
        for (int r = 0; r < 8; r++) {
            const int tok = wp * 8 + r;
            const int k = g_idx[n0 + tok];
            const float4* src = (const float4*)(w + (size_t)k * CC);
            #pragma unroll
            for (int j = 0; j < 2; j++) {
                const int i = lane + j * 32;      // 0..63 f4
                float4 v = __ldg(&src[i]);
                float* dst = &wstg[tok * 257 + i * 4];
                dst[0] = v.x; dst[1] = v.y; dst[2] = v.z; dst[3] = v.w;
            }
        }
    }
    __syncthreads();

    const int tok = t & 63;
    const int cq  = t >> 6;
    double s = 0.0;
    #pragma unroll 16
    for (int cc = 0; cc < 64; cc++) {
        const int c = cq * 64 + cc;
        const size_t g = ((size_t)b * CC + c) * HW + hw0 + tok;
        const float v = wstg[tok * 257 + c];
        const float zv = z[g];
        out[g] = v;
        const float d = zv - v;
        s += (double)d * (double)d;
    }
    #pragma unroll
    for (int o = 16; o; o >>= 1) s += __shfl_xor_sync(0xffffffffu, s, o);
    __shared__ double bs[8];
    const int lane = t & 31, wd = t >> 5;
    if (lane == 0) bs[wd] = s;
    __syncthreads();
    if (t == 0) {
        double tot = 0.0;
        #pragma unroll
        for (int i = 0; i < 8; i++) tot += bs[i];
        atomicAdd(&g_loss, tot);
    }
}

__global__ void finalize_kernel(float* __restrict__ out, int out_size) {
    float loss = (float)(g_loss * (1.0 / (double)NQ));
    if (out_size >= NQ + 1) out[NQ] = loss;
    if (out_size >= NQ + 2) out[NQ + 1] = loss;
}

// ---------------------------------------------------------------------------
extern "C" void kernel_launch(void* const* d_in, const int* in_sizes, int n_in,
                              void* d_out, int out_size) {
    const float* z = (const float*)d_in[0];
    const float* w = (const float*)d_in[1];
    float* out = (float*)d_out;

    const int smem_mma = (16384 + 4096 + 1024) * 4;   // 86016 B
    const int smem_cln = 256 * 128 * 4;               // 131072 B
    const int smem_gth = 64 * 257 * 4;                // 65792 B
    cudaFuncSetAttribute(mma_argmin_kernel,
                         cudaFuncAttributeMaxDynamicSharedMemorySize, smem_mma);
    cudaFuncSetAttribute(cleanup_kernel,
                         cudaFuncAttributeMaxDynamicSharedMemorySize, smem_cln);
    cudaFuncSetAttribute(gather_kernel,
                         cudaFuncAttributeMaxDynamicSharedMemorySize, smem_gth);

    wnorm_kernel<<<KK / 8, 256>>>(w);
    zn2_kernel<<<NTOT / 256, 256>>>(z);
    wpack_kernel<<<256, 256>>>(w);
    mma_argmin_kernel<<<NTOT / 128, 256, smem_mma>>>(z, w);
    cleanup_kernel<<<NTOT / 128, 128, smem_cln>>>(z, w);
    gather_kernel<<<NTOT / 64, 256, smem_gth>>>(z, w, out);
    finalize_kernel<<<1, 1>>>(out, out_size);
}

// round 16
// speedup vs baseline: 4.3644x; 1.0267x over previous
#include <cuda_runtime.h>
#include <cuda_bf16.h>
#include <cstdint>

// Problem constants
#define BB      32
#define CC      256
#define HW      1024
#define NTOT    32768          // BB*HW
#define KK      1024
#define NQ      8388608        // BB*CC*HW
#define MARGIN  4e-4f

typedef unsigned long long u64;

// Scratch (static device globals only — no runtime alloc)
__device__ double   g_loss;
__device__ int      g_idx[NTOT];
__device__ float    g_wnorm[KK];
__device__ float    g_zn2[NTOT];
__device__ uint32_t g_wpack[131072];     // 1024x256 bf16, fragment-ordered (512KB)
__device__ int      g_cand[NTOT * 8];    // candidate ks for status-1 tokens
__device__ int      g_stat[NTOT];        // 0=done, 1=rescore cands, 2=full scan

// ---------------------------------------------------------------------------
// Kernel 1: ||w_k||^2 — warp per row (coalesced), double reduce + loss init
// ---------------------------------------------------------------------------
__global__ void wnorm_kernel(const float* __restrict__ w) {
    const int k    = blockIdx.x * 8 + (threadIdx.x >> 5);
    const int lane = threadIdx.x & 31;
    if (blockIdx.x == 0 && threadIdx.x == 0) g_loss = 0.0;
    const float* row = w + (size_t)k * CC;
    double s = 0.0;
    #pragma unroll
    for (int i = 0; i < CC / 32; i++) {
        double v = (double)row[lane + i * 32];
        s += v * v;
    }
    #pragma unroll
    for (int o = 16; o; o >>= 1) s += __shfl_xor_sync(0xffffffffu, s, o);
    if (lane == 0) g_wnorm[k] = (float)s;
}

// ---------------------------------------------------------------------------
// Kernel 2: zn2 — exact XLA row-reduce emulation. DO NOT CHANGE (rel_err 0.0).
// ---------------------------------------------------------------------------
__global__ void zn2_kernel(const float* __restrict__ z) {
    const int n  = blockIdx.x * 256 + threadIdx.x;
    const int b  = n >> 10;
    const int hw = n & (HW - 1);
    const float* row = z + (size_t)b * (CC * HW) + hw;
    float W[4];
    #pragma unroll
    for (int w4 = 0; w4 < 4; w4++) {
        float p[32];
        #pragma unroll
        for (int l = 0; l < 32; l++) {
            float a = row[(size_t)(64 * w4 + 2 * l) * HW];
            float c = row[(size_t)(64 * w4 + 2 * l + 1) * HW];
            p[l] = __fadd_rn(__fmul_rn(a, a), __fmul_rn(c, c));
        }
        #pragma unroll
        for (int off = 16; off >= 1; off >>= 1)
            #pragma unroll
            for (int l = 0; l < 16; l++)
                if (l < off) p[l] = __fadd_rn(p[l], p[l + off]);
        W[w4] = p[0];
    }
    g_zn2[n] = __fadd_rn(__fadd_rn(W[0], W[2]), __fadd_rn(W[1], W[3]));
}

// ---------------------------------------------------------------------------
// Kernel 3: pack w into mma B-fragment order (bf16).
// ---------------------------------------------------------------------------
__global__ void wpack_kernel(const float* __restrict__ w) {
    int idx = blockIdx.x * 256 + threadIdx.x;        // 65536 slots
    int t = idx & 31, ks = (idx >> 5) & 15, nb = idx >> 9;
    int code = nb * 8 + (t >> 2);
    int c = t & 3;
    int d0 = ks * 16 + 2 * c;
    const float* wr = w + (size_t)code * CC;
    __nv_bfloat162 r0 = __floats2bfloat162_rn(wr[d0],     wr[d0 + 1]);
    __nv_bfloat162 r1 = __floats2bfloat162_rn(wr[d0 + 8], wr[d0 + 9]);
    g_wpack[idx * 2]     = *(uint32_t*)&r0;
    g_wpack[idx * 2 + 1] = *(uint32_t*)&r1;
}

// ---------------------------------------------------------------------------
// Kernel 4: bf16 mma.sync argmin v3 — 256 threads / 8 warps, 16 tokens/warp,
// B tile staged in SMEM once per CTA per nt (8x less L2 traffic).
// Smem (u32): apack [0,16384) | bstage [16384,24576) (overlaps A-pack stage)
//             | wns [24576,25600)
// ---------------------------------------------------------------------------
#define UPD(h, s, k) do { \
    if ((s) < v1[h]) { v3[h] = v2[h]; v2[h] = v1[h]; k2[h] = k1[h]; \
        v1[h] = (s); k1[h] = (k); } \
    else if ((s) < v2[h]) { v3[h] = v2[h]; v2[h] = (s); k2[h] = (k); } \
    else if ((s) < v3[h]) { v3[h] = (s); } \
} while (0)

#define MMA_BF16(C, A, b0, b1) \
    asm volatile("mma.sync.aligned.m16n8k16.row.col.f32.bf16.bf16.f32 " \
        "{%0,%1,%2,%3}, {%4,%5,%6,%7}, {%8,%9}, {%0,%1,%2,%3};" \
        : "+f"((C)[0]), "+f"((C)[1]), "+f"((C)[2]), "+f"((C)[3]) \
        : "r"((A).x), "r"((A).y), "r"((A).z), "r"((A).w), "r"(b0), "r"(b1))

__global__ __launch_bounds__(256, 2)
void mma_argmin_kernel(const float* __restrict__ z, const float* __restrict__ w) {
    extern __shared__ uint32_t smu[];
    uint32_t* apack  = smu;                       // 16384 u32 (64KB)
    uint32_t* bstage = smu + 16384;               // 8192 u32 (32KB)
    float*    stage  = (float*)(smu + 16384);     // 4096 f (A-pack only)
    float*    wns    = (float*)(smu + 24576);     // 1024 f (4KB)

    const int t = threadIdx.x, wp = t >> 5, lane = t & 31;
    const int c4 = lane & 3;
    const int n0  = blockIdx.x * 128;
    const int b   = blockIdx.x >> 3;
    const int hw0 = (blockIdx.x & 7) * 128;
    const float* zb = z + (size_t)b * (CC * HW) + hw0;

    #pragma unroll
    for (int j = 0; j < 4; j++) wns[j * 256 + t] = g_wnorm[j * 256 + t];

    // ---- pack A (z rows) into fragment-ordered bf16 smem, 32-d chunks ----
    for (int cd = 0; cd < 8; cd++) {
        __syncthreads();
        #pragma unroll
        for (int j = 0; j < 4; j++) {
            int fi = j * 256 + t;                 // 1024 float4 chunks
            int dl = fi >> 5, h4 = fi & 31;
            *(float4*)&stage[dl * 128 + h4 * 4] =
                *(const float4*)&zb[(size_t)(cd * 32 + dl) * HW + h4 * 4];
        }
        __syncthreads();
        #pragma unroll
        for (int i = 0; i < 8; i++) {
            int slot = i * 256 + t;               // 2048 slots
            int ai = slot & 3, tid2 = (slot >> 2) & 31;
            int rp = (slot >> 7) & 1, wp2 = (slot >> 8) & 3, ksl = (slot >> 10) & 1;
            int tok  = wp2 * 32 + rp * 16 + (ai & 1) * 8 + (tid2 >> 2);
            int dloc = ksl * 16 + ((ai >> 1) & 1) * 8 + 2 * (tid2 & 3);
            __nv_bfloat162 v = __floats2bfloat162_rn(stage[dloc * 128 + tok],
                                                     stage[(dloc + 1) * 128 + tok]);
            int ks = cd * 2 + ksl;
            apack[(ks * 8 + wp2 * 2 + rp) * 128 + tid2 * 4 + ai] = *(uint32_t*)&v;
        }
    }

    const uint4* ap4 = (const uint4*)apack;
    const uint2* bs2 = (const uint2*)bstage;
    uint4*       bd4 = (uint4*)bstage;

    float v1[2], v2[2], v3[2];
    int   k1[2], k2[2];
    #pragma unroll
    for (int h = 0; h < 2; h++) {
        v1[h] = v2[h] = v3[h] = 1e30f;
        k1[h] = k2[h] = 0x7fffffff;
    }

    for (int nt = 0; nt < 16; nt++) {
        __syncthreads();                          // prev tile consumed (and A-pack done, nt=0)
        // ---- stage B tile (32KB) cooperatively: straight uint4 copy ----
        const uint4* bsrc = (const uint4*)g_wpack + nt * 2048;
        #pragma unroll
        for (int j = 0; j < 8; j++)
            bd4[j * 256 + t] = __ldg(&bsrc[j * 256 + t]);
        __syncthreads();

        float acc[8][4];
        #pragma unroll
        for (int nb = 0; nb < 8; nb++)
            #pragma unroll
            for (int r = 0; r < 4; r++) acc[nb][r] = 0.f;

        // software pipeline over ks with smem-resident fragments
        uint4 A = ap4[(0 * 8 + wp) * 32 + lane];
        uint2 Bv[8];
        #pragma unroll
        for (int nb = 0; nb < 8; nb++)
            Bv[nb] = bs2[(nb * 16 + 0) * 32 + lane];

        #pragma unroll
        for (int ks = 0; ks < 16; ks++) {
            uint4 An;
            uint2 Bn[8];
            if (ks < 15) {
                An = ap4[((ks + 1) * 8 + wp) * 32 + lane];
                #pragma unroll
                for (int nb = 0; nb < 8; nb++)
                    Bn[nb] = bs2[(nb * 16 + ks + 1) * 32 + lane];
            }
            #pragma unroll
            for (int nb = 0; nb < 8; nb++)
                MMA_BF16(acc[nb], A, Bv[nb].x, Bv[nb].y);
            if (ks < 15) {
                A = An;
                #pragma unroll
                for (int nb = 0; nb < 8; nb++) Bv[nb] = Bn[nb];
            }
        }

        // epilogue: s = wn - 2*dot; per-thread top-2(+3rd) tracking
        #pragma unroll
        for (int nb = 0; nb < 8; nb++) {
            int kb = nt * 64 + nb * 8 + 2 * c4;
            float2 wnp = *(const float2*)&wns[kb];
            float s0 = __fmaf_rn(-2.f, acc[nb][0], wnp.x);
            float s1 = __fmaf_rn(-2.f, acc[nb][1], wnp.y);
            float s2 = __fmaf_rn(-2.f, acc[nb][2], wnp.x);
            float s3 = __fmaf_rn(-2.f, acc[nb][3], wnp.y);
            UPD(0, s0, kb); UPD(0, s1, kb + 1);
            UPD(1, s2, kb); UPD(1, s3, kb + 1);
        }
    }

    // ---- per token-row: quad-combine, certify or hand off ----
    #pragma unroll
    for (int h = 0; h < 2; h++) {
        float gm = v1[h];
        gm = fminf(gm, __shfl_xor_sync(0xffffffffu, gm, 1));
        gm = fminf(gm, __shfl_xor_sync(0xffffffffu, gm, 2));
        float thr = gm + MARGIN;
        int c1 = v1[h] <= thr;
        int c2 = v2[h] <= thr;
        int ov = v3[h] <= thr;
        int tot = c1 + c2;
        tot += __shfl_xor_sync(0xffffffffu, tot, 1);
        tot += __shfl_xor_sync(0xffffffffu, tot, 2);
        ov |= __shfl_xor_sync(0xffffffffu, ov, 1);
        ov |= __shfl_xor_sync(0xffffffffu, ov, 2);
        int kw = c1 ? k1[h] : 0x7fffffff;
        kw = min(kw, __shfl_xor_sync(0xffffffffu, kw, 1));
        kw = min(kw, __shfl_xor_sync(0xffffffffu, kw, 2));
        int n  = n0 + wp * 16 + h * 8 + (lane >> 2);
        int st = ov ? 2 : (tot == 1 ? 0 : 1);
        if (st == 1) {
            g_cand[n * 8 + c4 * 2]     = c1 ? k1[h] : -1;
            g_cand[n * 8 + c4 * 2 + 1] = c2 ? k2[h] : -1;
        }
        if (c4 == 0) {
            if (st == 0) g_idx[n] = kw;
            g_stat[n] = st;
        }
    }
}

// ---------------------------------------------------------------------------
// Kernel 5: cleanup v3 — tile-staged exact rescore, float4 w reads.
// ---------------------------------------------------------------------------
__global__ __launch_bounds__(128, 1)
void cleanup_kernel(const float* __restrict__ z, const float* __restrict__ w) {
    extern __shared__ float zs[];          // [256][128] fp32 = 128KB
    __shared__ int   s2list[128];
    __shared__ int   s2cnt;
    __shared__ float rv[128];
    __shared__ int   rk[128];

    const int t   = threadIdx.x;
    const int n0  = blockIdx.x * 128;
    const int b   = blockIdx.x >> 3;
    const int hw0 = (blockIdx.x & 7) * 128;
    const float* zb = z + (size_t)b * (CC * HW) + hw0;

    if (t == 0) s2cnt = 0;
    const int st = g_stat[n0 + t];
    if (!__syncthreads_or(st != 0)) return;     // whole tile certified

    #pragma unroll
    for (int j = 0; j < 64; j++) {
        int idx = j * 128 + t;                  // 0..8191 float4 chunks
        int d = idx >> 5, h4 = idx & 31;
        *(float4*)&zs[d * 128 + h4 * 4] = *(const float4*)&zb[(size_t)d * HW + h4 * 4];
    }
    __syncthreads();

    const int n = n0 + t;
    if (st == 1) {
        const float zn2v = g_zn2[n];
        float bv = 1e30f; int bk = 0x7fffffff;
        #pragma unroll
        for (int c = 0; c < 8; c++) {
            int k = g_cand[n * 8 + c];
            if (k < 0) continue;
            const float4* wr4 = (const float4*)(w + (size_t)k * CC);
            float acc = 0.f;
            #pragma unroll 16
            for (int i = 0; i < CC / 4; i++) {
                float4 v = __ldg(&wr4[i]);
                acc = __fmaf_rn(zs[(4 * i + 0) * 128 + t], v.x, acc);
                acc = __fmaf_rn(zs[(4 * i + 1) * 128 + t], v.y, acc);
                acc = __fmaf_rn(zs[(4 * i + 2) * 128 + t], v.z, acc);
                acc = __fmaf_rn(zs[(4 * i + 3) * 128 + t], v.w, acc);
            }
            float d2 = __fadd_rn(__fmaf_rn(-2.f, acc, zn2v), g_wnorm[k]);
            if (d2 < bv || (d2 == bv && k < bk)) { bv = d2; bk = k; }
        }
        g_idx[n] = bk;
    } else if (st == 2) {
        int p = atomicAdd(&s2cnt, 1);
        s2list[p] = t;
    }
    __syncthreads();

    const int cnt = s2cnt;
    for (int i = 0; i < cnt; i++) {
        const int tok = s2list[i];
        const float zn2v = g_zn2[n0 + tok];
        float bv = 1e30f; int bk = 0x7fffffff;
        #pragma unroll
        for (int j = 0; j < 8; j++) {
            int k = t * 8 + j;                   // ascending k per thread
            const float4* wr4 = (const float4*)(w + (size_t)k * CC);
            float acc = 0.f;
            #pragma unroll 16
            for (int i2 = 0; i2 < CC / 4; i2++) {
                float4 v = __ldg(&wr4[i2]);
                acc = __fmaf_rn(zs[(4 * i2 + 0) * 128 + tok], v.x, acc);
                acc = __fmaf_rn(zs[(4 * i2 + 1) * 128 + tok], v.y, acc);
                acc = __fmaf_rn(zs[(4 * i2 + 2) * 128 + tok], v.z, acc);
                acc = __fmaf_rn(zs[(4 * i2 + 3) * 128 + tok], v.w, acc);
            }
            float d2 = __fadd_rn(__fmaf_rn(-2.f, acc, zn2v), g_wnorm[k]);
            if (d2 < bv) { bv = d2; bk = k; }
        }
        rv[t] = bv; rk[t] = bk;
        __syncthreads();
        for (int off = 64; off >= 1; off >>= 1) {
            if (t < off) {
                float ov2 = rv[t + off]; int ok2 = rk[t + off];
                if (ov2 < rv[t] || (ov2 == rv[t] && ok2 < rk[t])) {
                    rv[t] = ov2; rk[t] = ok2;
                }
            }
            __syncthreads();
        }
        if (t == 0) g_idx[n0 + tok] = rk[0];
        __syncthreads();
    }
}

// ---------------------------------------------------------------------------
// Kernel 6: gather v2 — tile-staged. Block = 64 tokens, 256 threads.
// ---------------------------------------------------------------------------
__global__ __launch_bounds__(256, 1)
void gather_kernel(const float* __restrict__ z,
                   const float* __restrict__ w,
                   float* __restrict__ out) {
    extern __shared__ float wstg[];               // 64*257 floats
    const int t   = threadIdx.x;
    const int n0  = blockIdx.x * 64;              // 512 blocks
    const int b   = n0 >> 10;
    const int hw0 = n0 & (HW - 1);

    {
        const int wp = t >> 5, lane = t & 31;
        #pragma unroll
        for (int r = 0; r < 8; r++) {
            const int tok = wp * 8 + r;
            const int k = g_idx[n0 + tok];
            const float4* src = (const float4*)(w + (size_t)k * CC);
            #pragma unroll
            for (int j = 0; j < 2; j++) {
                const int i = lane + j * 32;      // 0..63 f4
                float4 v = __ldg(&src[i]);
                float* dst = &wstg[tok * 257 + i * 4];
                dst[0] = v.x; dst[1] = v.y; dst[2] = v.z; dst[3] = v.w;
            }
        }
    }
    __syncthreads();

    const int tok = t & 63;
    const int cq  = t >> 6;
    double s = 0.0;
    #pragma unroll 16
    for (int cc = 0; cc < 64; cc++) {
        const int c = cq * 64 + cc;
        const size_t g = ((size_t)b * CC + c) * HW + hw0 + tok;
        const float v = wstg[tok * 257 + c];
        const float zv = z[g];
        out[g] = v;
        const float d = zv - v;
        s += (double)d * (double)d;
    }
    #pragma unroll
    for (int o = 16; o; o >>= 1) s += __shfl_xor_sync(0xffffffffu, s, o);
    __shared__ double bs[8];
    const int lane = t & 31, wd = t >> 5;
    if (lane == 0) bs[wd] = s;
    __syncthreads();
    if (t == 0) {
        double tot = 0.0;
        #pragma unroll
        for (int i = 0; i < 8; i++) tot += bs[i];
        atomicAdd(&g_loss, tot);
    }
}

__global__ void finalize_kernel(float* __restrict__ out, int out_size) {
    float loss = (float)(g_loss * (1.0 / (double)NQ));
    if (out_size >= NQ + 1) out[NQ] = loss;
    if (out_size >= NQ + 2) out[NQ + 1] = loss;
}

// ---------------------------------------------------------------------------
extern "C" void kernel_launch(void* const* d_in, const int* in_sizes, int n_in,
                              void* d_out, int out_size) {
    const float* z = (const float*)d_in[0];
    const float* w = (const float*)d_in[1];
    float* out = (float*)d_out;

    const int smem_mma = (16384 + 8192 + 1024) * 4;   // 102400 B
    const int smem_cln = 256 * 128 * 4;               // 131072 B
    const int smem_gth = 64 * 257 * 4;                // 65792 B
    cudaFuncSetAttribute(mma_argmin_kernel,
                         cudaFuncAttributeMaxDynamicSharedMemorySize, smem_mma);
    cudaFuncSetAttribute(cleanup_kernel,
                         cudaFuncAttributeMaxDynamicSharedMemorySize, smem_cln);
    cudaFuncSetAttribute(gather_kernel,
                         cudaFuncAttributeMaxDynamicSharedMemorySize, smem_gth);

    wnorm_kernel<<<KK / 8, 256>>>(w);
    zn2_kernel<<<NTOT / 256, 256>>>(z);
    wpack_kernel<<<256, 256>>>(w);
    mma_argmin_kernel<<<NTOT / 128, 256, smem_mma>>>(z, w);
    cleanup_kernel<<<NTOT / 128, 128, smem_cln>>>(z, w);
    gather_kernel<<<NTOT / 64, 256, smem_gth>>>(z, w, out);
    finalize_kernel<<<1, 1>>>(out, out_size);
}